// round 1
// baseline (speedup 1.0000x reference)
#include <cuda_runtime.h>
#include <math.h>

#define ED   1024
#define GH   1024
#define NL_  3
#define NH_  8
#define HD_  128
#define NN   2048
#define BB   1024
#define INV_TEMP 20.0f
#define LAPW 0.1

// ---------------- scratch (static device memory; no allocations) ----------------
__device__ float g_x[NN * GH];          // GNN node features (residual stream)
__device__ float g_Wh[NH_ * NN * HD_];  // per-head projected features
__device__ float g_s1[NH_ * NN];
__device__ float g_s2[NH_ * NN];
__device__ float g_hcat[NN * GH];       // concat-head GAT output (pre LN)
__device__ float g_G[NN * ED];          // graph_embeds
__device__ float g_LG[NN * ED];         // laplacian @ graph_embeds
__device__ float g_t1[BB * ED];         // MLP hidden
__device__ float g_q[BB * ED];
__device__ float g_p[BB * ED];
__device__ float g_S[BB * BB];          // q @ p^T (unscaled)
__device__ double g_acc[2];             // [0]=info_nce sum, [1]=lap sum

// ---------------- utility kernels ----------------
__global__ void zero_acc_kernel() { g_acc[0] = 0.0; g_acc[1] = 0.0; }

__global__ void copy_kernel(const float* __restrict__ src, float* __restrict__ dst, int n) {
    int i = blockIdx.x * blockDim.x + threadIdx.x;
    int stride = gridDim.x * blockDim.x;
    for (; i < n; i += stride) dst[i] = src[i];
}

// ---------------- SGEMM: C[M,N] = A[M,K] @ op(B) (+bias), batched via blockIdx.z ----------------
// TRANSB=false: B is [K,N] row-major. TRANSB=true: B is [N,K] row-major (C = A @ B^T).
// Requires M%64==0, N%64==0, K%16==0 (all shapes here satisfy this).
template <bool TRANSB>
__global__ void sgemm_kernel(const float* __restrict__ A, const float* __restrict__ B,
                             const float* __restrict__ bias, float* __restrict__ C,
                             int M, int N, int K, long sA, long sB, long sC) {
    A += (long)blockIdx.z * sA;
    B += (long)blockIdx.z * sB;
    C += (long)blockIdx.z * sC;

    __shared__ float As[16][64];
    __shared__ float Bs[16][68];

    const int tid = threadIdx.x;            // 256 threads
    const int row0 = blockIdx.y * 64;
    const int col0 = blockIdx.x * 64;
    const int tx = tid & 15, ty = tid >> 4; // 16x16 thread grid, 4x4 per thread

    float acc[4][4] = {};

    for (int k0 = 0; k0 < K; k0 += 16) {
        {   // A tile: 64 rows x 16 k, float4 per thread
            int ar = tid >> 2, ac = (tid & 3) << 2;
            float4 v = *(const float4*)(A + (long)(row0 + ar) * K + k0 + ac);
            As[ac + 0][ar] = v.x; As[ac + 1][ar] = v.y;
            As[ac + 2][ar] = v.z; As[ac + 3][ar] = v.w;
        }
        if (!TRANSB) {
            int br = tid >> 4, bc = (tid & 15) << 2;
            float4 v = *(const float4*)(B + (long)(k0 + br) * N + col0 + bc);
            Bs[br][bc + 0] = v.x; Bs[br][bc + 1] = v.y;
            Bs[br][bc + 2] = v.z; Bs[br][bc + 3] = v.w;
        } else {
            int bn = tid >> 2, bk = (tid & 3) << 2;
            float4 v = *(const float4*)(B + (long)(col0 + bn) * K + k0 + bk);
            Bs[bk + 0][bn] = v.x; Bs[bk + 1][bn] = v.y;
            Bs[bk + 2][bn] = v.z; Bs[bk + 3][bn] = v.w;
        }
        __syncthreads();

        #pragma unroll
        for (int k = 0; k < 16; k++) {
            float ra[4], rb[4];
            #pragma unroll
            for (int i = 0; i < 4; i++) ra[i] = As[k][ty * 4 + i];
            #pragma unroll
            for (int j = 0; j < 4; j++) rb[j] = Bs[k][tx * 4 + j];
            #pragma unroll
            for (int i = 0; i < 4; i++)
                #pragma unroll
                for (int j = 0; j < 4; j++) acc[i][j] += ra[i] * rb[j];
        }
        __syncthreads();
    }

    #pragma unroll
    for (int i = 0; i < 4; i++) {
        int r = row0 + ty * 4 + i;
        #pragma unroll
        for (int j = 0; j < 4; j++) {
            int c = col0 + tx * 4 + j;
            float v = acc[i][j];
            if (bias) v += bias[c];
            C[(long)r * N + c] = v;
        }
    }
}

// ---------------- GAT: s1/s2 scores (one warp per (h,n)) ----------------
__global__ void s12_kernel(const float* __restrict__ a1, const float* __restrict__ a2) {
    int warp = (blockIdx.x * blockDim.x + threadIdx.x) >> 5;
    int lane = threadIdx.x & 31;
    if (warp >= NH_ * NN) return;
    int h = warp / NN;
    const float* w = g_Wh + (long)warp * HD_;
    const float* A1 = a1 + h * HD_;
    const float* A2 = a2 + h * HD_;
    float d1 = 0.f, d2 = 0.f;
    #pragma unroll
    for (int i = lane; i < HD_; i += 32) { float v = w[i]; d1 += v * A1[i]; d2 += v * A2[i]; }
    #pragma unroll
    for (int o = 16; o > 0; o >>= 1) {
        d1 += __shfl_down_sync(0xffffffffu, d1, o);
        d2 += __shfl_down_sync(0xffffffffu, d2, o);
    }
    if (lane == 0) { g_s1[warp] = d1; g_s2[warp] = d2; }
}

// ---------------- GAT attention: sparse softmax + gather (block = (n, h), 128 thr) ----------------
__global__ void gat_attn_kernel(const float* __restrict__ adj) {
    const int n = blockIdx.x, h = blockIdx.y;
    const int tid = threadIdx.x;  // 128

    __shared__ int   cnt;
    __shared__ int   idx[NN];
    __shared__ float sc[NN];
    __shared__ float red[128];

    if (tid == 0) cnt = 0;
    __syncthreads();

    const float* arow = adj + (long)n * NN;
    for (int m = tid; m < NN; m += 128)
        if (arow[m] > 0.f) { int p = atomicAdd(&cnt, 1); idx[p] = m; }
    __syncthreads();

    const int c = cnt;
    const float s1n = g_s1[h * NN + n];

    float mx = -1e30f;
    for (int j = tid; j < c; j += 128) {
        float e = s1n + g_s2[h * NN + idx[j]];
        e = e > 0.f ? e : 0.2f * e;           // leaky_relu(0.2)
        sc[j] = e;
        mx = fmaxf(mx, e);
    }
    red[tid] = mx; __syncthreads();
    for (int o = 64; o > 0; o >>= 1) { if (tid < o) red[tid] = fmaxf(red[tid], red[tid + o]); __syncthreads(); }
    mx = red[0];
    __syncthreads();

    float sm = 0.f;
    for (int j = tid; j < c; j += 128) { float e = expf(sc[j] - mx); sc[j] = e; sm += e; }
    red[tid] = sm; __syncthreads();
    for (int o = 64; o > 0; o >>= 1) { if (tid < o) red[tid] += red[tid + o]; __syncthreads(); }
    const float inv = 1.f / red[0];

    // output feature dim = tid (HD_ == 128)
    float acc = 0.f;
    const float* whh = g_Wh + (long)h * NN * HD_;
    for (int j = 0; j < c; j++)
        acc += sc[j] * whh[(long)idx[j] * HD_ + tid];
    g_hcat[(long)n * GH + h * HD_ + tid] = acc * inv;
}

// ---------------- row-wise LN (+activation) kernels, row width 1024, 256 thr ----------------
__global__ void ln_gelu_kernel(float* __restrict__ x, const float* __restrict__ g,
                               const float* __restrict__ b) {
    const int row = blockIdx.x, tid = threadIdx.x;
    float* xr = x + (long)row * 1024;
    float v[4]; float s = 0.f, ss = 0.f;
    #pragma unroll
    for (int i = 0; i < 4; i++) { v[i] = xr[tid + i * 256]; s += v[i]; ss += v[i] * v[i]; }
    __shared__ float rs[256], rss[256];
    rs[tid] = s; rss[tid] = ss; __syncthreads();
    for (int o = 128; o > 0; o >>= 1) { if (tid < o) { rs[tid] += rs[tid + o]; rss[tid] += rss[tid + o]; } __syncthreads(); }
    float mean = rs[0] * (1.f / 1024.f);
    float var  = rss[0] * (1.f / 1024.f) - mean * mean;
    float rstd = rsqrtf(var + 1e-5f);
    #pragma unroll
    for (int i = 0; i < 4; i++) {
        int cidx = tid + i * 256;
        float t = (v[i] - mean) * rstd * g[cidx] + b[cidx];
        xr[cidx] = 0.5f * t * (1.f + erff(t * 0.70710678118654752f));  // exact gelu
    }
}

__global__ void ln_elu_res_kernel(const float* __restrict__ hin, const float* __restrict__ g,
                                  const float* __restrict__ b, float* __restrict__ x) {
    const int row = blockIdx.x, tid = threadIdx.x;
    const float* hr = hin + (long)row * 1024;
    float* xr = x + (long)row * 1024;
    float v[4]; float s = 0.f, ss = 0.f;
    #pragma unroll
    for (int i = 0; i < 4; i++) { v[i] = hr[tid + i * 256]; s += v[i]; ss += v[i] * v[i]; }
    __shared__ float rs[256], rss[256];
    rs[tid] = s; rss[tid] = ss; __syncthreads();
    for (int o = 128; o > 0; o >>= 1) { if (tid < o) { rs[tid] += rs[tid + o]; rss[tid] += rss[tid + o]; } __syncthreads(); }
    float mean = rs[0] * (1.f / 1024.f);
    float var  = rss[0] * (1.f / 1024.f) - mean * mean;
    float rstd = rsqrtf(var + 1e-5f);
    #pragma unroll
    for (int i = 0; i < 4; i++) {
        int cidx = tid + i * 256;
        float t = (v[i] - mean) * rstd * g[cidx] + b[cidx];
        t = t > 0.f ? t : expm1f(t);          // elu
        xr[cidx] += t;                        // residual
    }
}

__global__ void l2norm_kernel(float* __restrict__ x) {
    const int row = blockIdx.x, tid = threadIdx.x;
    float* xr = x + (long)row * 1024;
    float v[4]; float ss = 0.f;
    #pragma unroll
    for (int i = 0; i < 4; i++) { v[i] = xr[tid + i * 256]; ss += v[i] * v[i]; }
    __shared__ float rss[256];
    rss[tid] = ss; __syncthreads();
    for (int o = 128; o > 0; o >>= 1) { if (tid < o) rss[tid] += rss[tid + o]; __syncthreads(); }
    float nrm = sqrtf(rss[0]);
    float inv = 1.f / fmaxf(nrm, 1e-12f);
    #pragma unroll
    for (int i = 0; i < 4; i++) xr[tid + i * 256] = v[i] * inv;
}

// ---------------- InfoNCE: per-row logsumexp over [pos, row] ----------------
__global__ void infonce_kernel() {
    const int i = blockIdx.x, tid = threadIdx.x;  // 256 thr, BB rows
    const float* row = g_S + (long)i * BB;
    const float pos = row[i] * INV_TEMP;

    __shared__ float red[256];
    float mx = -1e30f;
    for (int j = tid; j < BB; j += 256) mx = fmaxf(mx, row[j] * INV_TEMP);
    red[tid] = mx; __syncthreads();
    for (int o = 128; o > 0; o >>= 1) { if (tid < o) red[tid] = fmaxf(red[tid], red[tid + o]); __syncthreads(); }
    mx = red[0];
    __syncthreads();

    float sm = 0.f;
    for (int j = tid; j < BB; j += 256) sm += expf(row[j] * INV_TEMP - mx);
    red[tid] = sm; __syncthreads();
    for (int o = 128; o > 0; o >>= 1) { if (tid < o) red[tid] += red[tid + o]; __syncthreads(); }

    if (tid == 0) {
        float total = red[0] + expf(pos - mx);   // duplicate pos logit (concat)
        float loss = logf(total) + mx - pos;
        atomicAdd(&g_acc[0], (double)loss);
    }
}

// ---------------- Laplacian regularizer: sum(G * LG) ----------------
__global__ void lapdot_kernel() {
    const int n = NN * ED;
    double local = 0.0;
    for (int i = blockIdx.x * blockDim.x + threadIdx.x; i < n; i += gridDim.x * blockDim.x)
        local += (double)g_G[i] * (double)g_LG[i];
    __shared__ double rd[256];
    rd[threadIdx.x] = local; __syncthreads();
    for (int o = 128; o > 0; o >>= 1) { if (threadIdx.x < o) rd[threadIdx.x] += rd[threadIdx.x + o]; __syncthreads(); }
    if (threadIdx.x == 0) atomicAdd(&g_acc[1], rd[0]);
}

__global__ void finalize_kernel(float* out, int out_size) {
    double info = g_acc[0] / (double)BB;
    double lap  = g_acc[1] / (double)NN;
    double vals[3] = { info + LAPW * lap, info, lap };
    for (int i = 0; i < out_size && i < 3; i++) out[i] = (float)vals[i];
}

// ---------------- launch ----------------
extern "C" void kernel_launch(void* const* d_in, const int* in_sizes, int n_in,
                              void* d_out, int out_size) {
    const float* query = (const float*)d_in[0];
    const float* doc   = (const float*)d_in[1];
    const float* node  = (const float*)d_in[2];
    const float* adj   = (const float*)d_in[3];
    const float* lapl  = (const float*)d_in[4];
    const float* qW1 = (const float*)d_in[5];  const float* qb1 = (const float*)d_in[6];
    const float* qg  = (const float*)d_in[7];  const float* qbt = (const float*)d_in[8];
    const float* qW2 = (const float*)d_in[9];  const float* qb2 = (const float*)d_in[10];
    const float* dW1 = (const float*)d_in[11]; const float* db1 = (const float*)d_in[12];
    const float* dg  = (const float*)d_in[13]; const float* dbt = (const float*)d_in[14];
    const float* dW2 = (const float*)d_in[15]; const float* db2 = (const float*)d_in[16];
    const float* gatW = (const float*)d_in[17];
    const float* a1   = (const float*)d_in[18];
    const float* a2   = (const float*)d_in[19];
    const float* ln_g = (const float*)d_in[20];
    const float* ln_b = (const float*)d_in[21];
    const float* poW  = (const float*)d_in[22];
    const float* pob  = (const float*)d_in[23];
    float* out = (float*)d_out;

    float *px, *pWh, *phcat, *pG, *pLG, *pt1, *pq, *pp, *pS;
    cudaGetSymbolAddress((void**)&px,    g_x);
    cudaGetSymbolAddress((void**)&pWh,   g_Wh);
    cudaGetSymbolAddress((void**)&phcat, g_hcat);
    cudaGetSymbolAddress((void**)&pG,    g_G);
    cudaGetSymbolAddress((void**)&pLG,   g_LG);
    cudaGetSymbolAddress((void**)&pt1,   g_t1);
    cudaGetSymbolAddress((void**)&pq,    g_q);
    cudaGetSymbolAddress((void**)&pp,    g_p);
    cudaGetSymbolAddress((void**)&pS,    g_S);

    zero_acc_kernel<<<1, 1>>>();
    copy_kernel<<<2048, 512>>>(node, px, NN * GH);

    // ---- GNN layers ----
    for (int l = 0; l < NL_; l++) {
        // Wh[h] = x @ gatW[l,h]   (batched over 8 heads)
        sgemm_kernel<false><<<dim3(HD_ / 64, NN / 64, NH_), 256>>>(
            px, gatW + (long)l * NH_ * ED * HD_, nullptr, pWh,
            NN, HD_, GH, 0L, (long)ED * HD_, (long)NN * HD_);
        s12_kernel<<<(NH_ * NN * 32 + 255) / 256, 256>>>(a1 + l * NH_ * HD_, a2 + l * NH_ * HD_);
        gat_attn_kernel<<<dim3(NN, NH_), 128>>>(adj);
        ln_elu_res_kernel<<<NN, 256>>>(phcat, ln_g + l * GH, ln_b + l * GH, px);
    }

    // graph_embeds = x @ poW + pob
    sgemm_kernel<false><<<dim3(ED / 64, NN / 64, 1), 256>>>(px, poW, pob, pG, NN, ED, GH, 0L, 0L, 0L);
    // LG = laplacian @ G
    sgemm_kernel<false><<<dim3(ED / 64, NN / 64, 1), 256>>>(lapl, pG, nullptr, pLG, NN, ED, NN, 0L, 0L, 0L);
    lapdot_kernel<<<2048, 256>>>();

    // ---- query MLP ----
    sgemm_kernel<false><<<dim3(ED / 64, BB / 64, 1), 256>>>(query, qW1, qb1, pt1, BB, ED, ED, 0L, 0L, 0L);
    ln_gelu_kernel<<<BB, 256>>>(pt1, qg, qbt);
    sgemm_kernel<false><<<dim3(ED / 64, BB / 64, 1), 256>>>(pt1, qW2, qb2, pq, BB, ED, ED, 0L, 0L, 0L);
    l2norm_kernel<<<BB, 256>>>(pq);

    // ---- doc MLP ----
    sgemm_kernel<false><<<dim3(ED / 64, BB / 64, 1), 256>>>(doc, dW1, db1, pt1, BB, ED, ED, 0L, 0L, 0L);
    ln_gelu_kernel<<<BB, 256>>>(pt1, dg, dbt);
    sgemm_kernel<false><<<dim3(ED / 64, BB / 64, 1), 256>>>(pt1, dW2, db2, pp, BB, ED, ED, 0L, 0L, 0L);
    l2norm_kernel<<<BB, 256>>>(pp);

    // ---- similarities + losses ----
    sgemm_kernel<true><<<dim3(BB / 64, BB / 64, 1), 256>>>(pq, pp, nullptr, pS, BB, BB, ED, 0L, 0L, 0L);
    infonce_kernel<<<BB, 256>>>();

    finalize_kernel<<<1, 1>>>(out, out_size);
}

// round 3
// speedup vs baseline: 1.5505x; 1.5505x over previous
#include <cuda_runtime.h>
#include <math.h>
#include <stdint.h>

#define ED   1024
#define GH   1024
#define NL_  3
#define NH_  8
#define HD_  128
#define NN   2048
#define BB   1024
#define INV_TEMP 20.0f
#define LAPW 0.1
#define MAXD 2048

// ---------------- scratch (static device memory; no allocations) ----------------
__device__ float g_x[NN * GH];          // GNN node features (residual stream)
__device__ float g_Wh[NH_ * NN * HD_];  // per-head projected features
__device__ float g_s1[NH_ * NN];
__device__ float g_s2[NH_ * NN];
__device__ float g_hcat[NN * GH];       // concat-head GAT output (pre LN)
__device__ float g_G[NN * ED];          // graph_embeds
__device__ float g_LG[NN * ED];         // laplacian @ graph_embeds
__device__ float g_t1[BB * ED];         // MLP hidden
__device__ float g_q[BB * ED];
__device__ float g_p[BB * ED];
__device__ float g_S[BB * BB];          // q @ p^T (unscaled)
__device__ int   g_ncnt[NN];
__device__ int   g_nidx[NN * MAXD];
__device__ double g_acc[2];             // [0]=info_nce sum, [1]=lap sum

// ---------------- utility kernels ----------------
__global__ void zero_acc_kernel() { g_acc[0] = 0.0; g_acc[1] = 0.0; }

__global__ void copy_kernel(const float* __restrict__ src, float* __restrict__ dst, int n) {
    int i = blockIdx.x * blockDim.x + threadIdx.x;
    int stride = gridDim.x * blockDim.x;
    for (; i < n; i += stride) dst[i] = src[i];
}

// ---------------- tf32 helpers ----------------
__device__ __forceinline__ uint32_t f2tf(float f) {
    uint32_t u;
    asm volatile("cvt.rna.tf32.f32 %0, %1;" : "=r"(u) : "f"(f));
    return u;
}

__device__ __forceinline__ void cpasync16(void* smem, const void* gmem) {
    uint32_t s = (uint32_t)__cvta_generic_to_shared(smem);
    asm volatile("cp.async.cg.shared.global [%0], [%1], 16;" :: "r"(s), "l"(gmem));
}
#define CP_COMMIT() asm volatile("cp.async.commit_group;")
#define CP_WAIT1()  asm volatile("cp.async.wait_group 1;")
#define CP_WAIT0()  asm volatile("cp.async.wait_group 0;")

#define MMA_TF32(c0,c1,c2,c3, a0,a1,a2,a3, b0,b1)                                   \
    asm volatile("mma.sync.aligned.m16n8k8.row.col.f32.tf32.tf32.f32 "              \
        "{%0,%1,%2,%3}, {%4,%5,%6,%7}, {%8,%9}, {%0,%1,%2,%3};"                     \
        : "+f"(c0), "+f"(c1), "+f"(c2), "+f"(c3)                                    \
        : "r"(a0), "r"(a1), "r"(a2), "r"(a3), "r"(b0), "r"(b1))

// ---------------- tensor-core GEMM: C[M,N] = A[M,K] @ op(B) (+bias) ----------------
// BM=128, BN=128, BK=16; 256 threads = 8 warps (2m x 4n), warp tile 64x32.
// TRANSB=false: B row-major [K,N]; TRANSB=true: B row-major [N,K] (C = A @ B^T).
// Requires M%128==0, N%128==0, K%16==0.
template <bool TRANSB>
__global__ void __launch_bounds__(256)
mma_gemm(const float* __restrict__ A, const float* __restrict__ B,
         const float* __restrict__ bias, float* __restrict__ C,
         int M, int N, int K, long sA, long sB, long sC) {
    A += (long)blockIdx.z * sA;
    B += (long)blockIdx.z * sB;
    C += (long)blockIdx.z * sC;

    // As: [2][128][20] (row-major m x k, pad->conflict-free fragment LDS)
    // Bs: !TRANSB -> [2][16][136] (k x n), TRANSB -> [2][128][20] (n x k)
    __shared__ __align__(16) float As[2][128][20];
    __shared__ __align__(16) float Bs[2 * 2560];

    const int tid  = threadIdx.x;
    const int lane = tid & 31;
    const int w    = tid >> 5;
    const int wm   = (w >> 2) * 64;  // 0 or 64
    const int wn   = (w & 3) * 32;   // 0,32,64,96
    const int g    = lane >> 2;      // 0..7
    const int tq   = lane & 3;       // 0..3

    const int row0 = blockIdx.y * 128;
    const int col0 = blockIdx.x * 128;

    float acc[4][4][4];
    #pragma unroll
    for (int mi = 0; mi < 4; mi++)
        #pragma unroll
        for (int ni = 0; ni < 4; ni++)
            #pragma unroll
            for (int e = 0; e < 4; e++) acc[mi][ni][e] = 0.f;

    const int tiles = K >> 4;

    // issue loads for a tile into buffer `buf`
    auto load_tile = [&](int t, int buf) {
        const int k0 = t << 4;
        #pragma unroll
        for (int c = 0; c < 2; c++) {  // A: 128x16 = 512 float4 chunks
            int i  = c * 256 + tid;
            int r  = i >> 2;
            int k4 = (i & 3) << 2;
            cpasync16(&As[buf][r][k4], A + (long)(row0 + r) * K + k0 + k4);
        }
        if (!TRANSB) {
            #pragma unroll
            for (int c = 0; c < 2; c++) {  // B: 16x128
                int i  = c * 256 + tid;
                int r  = i >> 5;
                int n4 = (i & 31) << 2;
                cpasync16(&Bs[buf * 2560 + r * 136 + n4],
                          B + (long)(k0 + r) * N + col0 + n4);
            }
        } else {
            #pragma unroll
            for (int c = 0; c < 2; c++) {  // B^T tile: 128 n-rows x 16 k
                int i  = c * 256 + tid;
                int r  = i >> 2;
                int k4 = (i & 3) << 2;
                cpasync16(&Bs[buf * 2560 + r * 20 + k4],
                          B + (long)(col0 + r) * K + k0 + k4);
            }
        }
    };

    load_tile(0, 0);
    CP_COMMIT();

    int buf = 0;
    for (int t = 0; t < tiles; t++) {
        if (t + 1 < tiles) { load_tile(t + 1, buf ^ 1); CP_COMMIT(); CP_WAIT1(); }
        else               { CP_WAIT0(); }
        __syncthreads();

        #pragma unroll
        for (int kk = 0; kk < 2; kk++) {
            const int kb = kk * 8;
            uint32_t af[4][4];
            #pragma unroll
            for (int mi = 0; mi < 4; mi++) {
                const float* ap = &As[buf][wm + mi * 16][0];
                af[mi][0] = f2tf(ap[(g)     * 20 + kb + tq]);
                af[mi][1] = f2tf(ap[(g + 8) * 20 + kb + tq]);
                af[mi][2] = f2tf(ap[(g)     * 20 + kb + tq + 4]);
                af[mi][3] = f2tf(ap[(g + 8) * 20 + kb + tq + 4]);
            }
            uint32_t bfr[4][2];
            #pragma unroll
            for (int ni = 0; ni < 4; ni++) {
                int col = wn + ni * 8 + g;
                if (!TRANSB) {
                    bfr[ni][0] = f2tf(Bs[buf * 2560 + (kb + tq)     * 136 + col]);
                    bfr[ni][1] = f2tf(Bs[buf * 2560 + (kb + tq + 4) * 136 + col]);
                } else {
                    bfr[ni][0] = f2tf(Bs[buf * 2560 + col * 20 + kb + tq]);
                    bfr[ni][1] = f2tf(Bs[buf * 2560 + col * 20 + kb + tq + 4]);
                }
            }
            #pragma unroll
            for (int mi = 0; mi < 4; mi++)
                #pragma unroll
                for (int ni = 0; ni < 4; ni++)
                    MMA_TF32(acc[mi][ni][0], acc[mi][ni][1], acc[mi][ni][2], acc[mi][ni][3],
                             af[mi][0], af[mi][1], af[mi][2], af[mi][3],
                             bfr[ni][0], bfr[ni][1]);
        }
        __syncthreads();
        buf ^= 1;
    }

    // epilogue
    #pragma unroll
    for (int mi = 0; mi < 4; mi++) {
        int r0 = row0 + wm + mi * 16 + g;
        #pragma unroll
        for (int ni = 0; ni < 4; ni++) {
            int cb = col0 + wn + ni * 8 + 2 * tq;
            float b0 = bias ? bias[cb]     : 0.f;
            float b1 = bias ? bias[cb + 1] : 0.f;
            float2 v0 = make_float2(acc[mi][ni][0] + b0, acc[mi][ni][1] + b1);
            float2 v1 = make_float2(acc[mi][ni][2] + b0, acc[mi][ni][3] + b1);
            *(float2*)(C + (long)r0 * N + cb)       = v0;
            *(float2*)(C + (long)(r0 + 8) * N + cb) = v1;
        }
    }
}

// ---------------- adjacency compaction (once per call, reused 24x) ----------------
__global__ void compact_adj_kernel(const float* __restrict__ adj) {
    const int n = blockIdx.x;
    __shared__ int cnt;
    if (threadIdx.x == 0) cnt = 0;
    __syncthreads();
    const float* row = adj + (long)n * NN;
    for (int m = threadIdx.x; m < NN; m += blockDim.x)
        if (row[m] > 0.f) { int p = atomicAdd(&cnt, 1); g_nidx[(long)n * MAXD + p] = m; }
    __syncthreads();
    if (threadIdx.x == 0) g_ncnt[n] = cnt;
}

// ---------------- GAT: s1/s2 scores (one warp per (h,n)) ----------------
__global__ void s12_kernel(const float* __restrict__ a1, const float* __restrict__ a2) {
    int warp = (blockIdx.x * blockDim.x + threadIdx.x) >> 5;
    int lane = threadIdx.x & 31;
    if (warp >= NH_ * NN) return;
    int h = warp / NN;
    const float* w = g_Wh + (long)warp * HD_;
    const float* A1 = a1 + h * HD_;
    const float* A2 = a2 + h * HD_;
    float d1 = 0.f, d2 = 0.f;
    #pragma unroll
    for (int i = lane; i < HD_; i += 32) { float v = w[i]; d1 += v * A1[i]; d2 += v * A2[i]; }
    #pragma unroll
    for (int o = 16; o > 0; o >>= 1) {
        d1 += __shfl_down_sync(0xffffffffu, d1, o);
        d2 += __shfl_down_sync(0xffffffffu, d2, o);
    }
    if (lane == 0) { g_s1[warp] = d1; g_s2[warp] = d2; }
}

// ---------------- GAT attention: sparse softmax + gather (block = (n, h), 128 thr) ----------------
__global__ void gat_attn_kernel() {
    const int n = blockIdx.x, h = blockIdx.y;
    const int tid = threadIdx.x;  // 128
    const int c = g_ncnt[n];
    const int* gidx = g_nidx + (long)n * MAXD;

    __shared__ float sc[MAXD];
    __shared__ int   sidx[MAXD];
    __shared__ float red[128];

    const float s1n = g_s1[h * NN + n];
    const float* s2h = g_s2 + h * NN;

    float mx = -1e30f;
    for (int j = tid; j < c; j += 128) {
        int m = gidx[j];
        sidx[j] = m;
        float e = s1n + s2h[m];
        e = e > 0.f ? e : 0.2f * e;           // leaky_relu(0.2)
        sc[j] = e;
        mx = fmaxf(mx, e);
    }
    red[tid] = mx; __syncthreads();
    for (int o = 64; o > 0; o >>= 1) { if (tid < o) red[tid] = fmaxf(red[tid], red[tid + o]); __syncthreads(); }
    mx = red[0];
    __syncthreads();

    float sm = 0.f;
    for (int j = tid; j < c; j += 128) { float e = expf(sc[j] - mx); sc[j] = e; sm += e; }
    red[tid] = sm; __syncthreads();
    for (int o = 64; o > 0; o >>= 1) { if (tid < o) red[tid] += red[tid + o]; __syncthreads(); }
    const float inv = 1.f / red[0];
    __syncthreads();

    // output feature dim = tid (HD_ == 128)
    float acc = 0.f;
    const float* whh = g_Wh + (long)h * NN * HD_;
    #pragma unroll 4
    for (int j = 0; j < c; j++)
        acc += sc[j] * whh[(long)sidx[j] * HD_ + tid];
    g_hcat[(long)n * GH + h * HD_ + tid] = acc * inv;
}

// ---------------- row-wise LN (+activation) kernels, row width 1024, 256 thr ----------------
__global__ void ln_gelu_kernel(float* __restrict__ x, const float* __restrict__ g,
                               const float* __restrict__ b) {
    const int row = blockIdx.x, tid = threadIdx.x;
    float* xr = x + (long)row * 1024;
    float v[4]; float s = 0.f, ss = 0.f;
    #pragma unroll
    for (int i = 0; i < 4; i++) { v[i] = xr[tid + i * 256]; s += v[i]; ss += v[i] * v[i]; }
    __shared__ float rs[256], rss[256];
    rs[tid] = s; rss[tid] = ss; __syncthreads();
    for (int o = 128; o > 0; o >>= 1) { if (tid < o) { rs[tid] += rs[tid + o]; rss[tid] += rss[tid + o]; } __syncthreads(); }
    float mean = rs[0] * (1.f / 1024.f);
    float var  = rss[0] * (1.f / 1024.f) - mean * mean;
    float rstd = rsqrtf(var + 1e-5f);
    #pragma unroll
    for (int i = 0; i < 4; i++) {
        int cidx = tid + i * 256;
        float t = (v[i] - mean) * rstd * g[cidx] + b[cidx];
        xr[cidx] = 0.5f * t * (1.f + erff(t * 0.70710678118654752f));  // exact gelu
    }
}

__global__ void ln_elu_res_kernel(const float* __restrict__ hin, const float* __restrict__ g,
                                  const float* __restrict__ b, float* __restrict__ x) {
    const int row = blockIdx.x, tid = threadIdx.x;
    const float* hr = hin + (long)row * 1024;
    float* xr = x + (long)row * 1024;
    float v[4]; float s = 0.f, ss = 0.f;
    #pragma unroll
    for (int i = 0; i < 4; i++) { v[i] = hr[tid + i * 256]; s += v[i]; ss += v[i] * v[i]; }
    __shared__ float rs[256], rss[256];
    rs[tid] = s; rss[tid] = ss; __syncthreads();
    for (int o = 128; o > 0; o >>= 1) { if (tid < o) { rs[tid] += rs[tid + o]; rss[tid] += rss[tid + o]; } __syncthreads(); }
    float mean = rs[0] * (1.f / 1024.f);
    float var  = rss[0] * (1.f / 1024.f) - mean * mean;
    float rstd = rsqrtf(var + 1e-5f);
    #pragma unroll
    for (int i = 0; i < 4; i++) {
        int cidx = tid + i * 256;
        float t = (v[i] - mean) * rstd * g[cidx] + b[cidx];
        t = t > 0.f ? t : expm1f(t);          // elu
        xr[cidx] += t;                        // residual
    }
}

__global__ void l2norm_kernel(float* __restrict__ x) {
    const int row = blockIdx.x, tid = threadIdx.x;
    float* xr = x + (long)row * 1024;
    float v[4]; float ss = 0.f;
    #pragma unroll
    for (int i = 0; i < 4; i++) { v[i] = xr[tid + i * 256]; ss += v[i] * v[i]; }
    __shared__ float rss[256];
    rss[tid] = ss; __syncthreads();
    for (int o = 128; o > 0; o >>= 1) { if (tid < o) rss[tid] += rss[tid + o]; __syncthreads(); }
    float nrm = sqrtf(rss[0]);
    float inv = 1.f / fmaxf(nrm, 1e-12f);
    #pragma unroll
    for (int i = 0; i < 4; i++) xr[tid + i * 256] = v[i] * inv;
}

// ---------------- InfoNCE: per-row logsumexp over [pos, row] ----------------
__global__ void infonce_kernel() {
    const int i = blockIdx.x, tid = threadIdx.x;  // 256 thr, BB rows
    const float* row = g_S + (long)i * BB;
    const float pos = row[i] * INV_TEMP;

    __shared__ float red[256];
    float mx = -1e30f;
    for (int j = tid; j < BB; j += 256) mx = fmaxf(mx, row[j] * INV_TEMP);
    red[tid] = mx; __syncthreads();
    for (int o = 128; o > 0; o >>= 1) { if (tid < o) red[tid] = fmaxf(red[tid], red[tid + o]); __syncthreads(); }
    mx = red[0];
    __syncthreads();

    float sm = 0.f;
    for (int j = tid; j < BB; j += 256) sm += expf(row[j] * INV_TEMP - mx);
    red[tid] = sm; __syncthreads();
    for (int o = 128; o > 0; o >>= 1) { if (tid < o) red[tid] += red[tid + o]; __syncthreads(); }

    if (tid == 0) {
        float total = red[0] + expf(pos - mx);   // duplicate pos logit (concat)
        float loss = logf(total) + mx - pos;
        atomicAdd(&g_acc[0], (double)loss);
    }
}

// ---------------- Laplacian regularizer: sum(G * LG) ----------------
__global__ void lapdot_kernel() {
    const int n = NN * ED;
    double local = 0.0;
    for (int i = blockIdx.x * blockDim.x + threadIdx.x; i < n; i += gridDim.x * blockDim.x)
        local += (double)g_G[i] * (double)g_LG[i];
    __shared__ double rd[256];
    rd[threadIdx.x] = local; __syncthreads();
    for (int o = 128; o > 0; o >>= 1) { if (threadIdx.x < o) rd[threadIdx.x] += rd[threadIdx.x + o]; __syncthreads(); }
    if (threadIdx.x == 0) atomicAdd(&g_acc[1], rd[0]);
}

__global__ void finalize_kernel(float* out, int out_size) {
    double info = g_acc[0] / (double)BB;
    double lap  = g_acc[1] / (double)NN;
    double vals[3] = { info + LAPW * lap, info, lap };
    for (int i = 0; i < out_size && i < 3; i++) out[i] = (float)vals[i];
}

// ---------------- launch ----------------
extern "C" void kernel_launch(void* const* d_in, const int* in_sizes, int n_in,
                              void* d_out, int out_size) {
    const float* query = (const float*)d_in[0];
    const float* doc   = (const float*)d_in[1];
    const float* node  = (const float*)d_in[2];
    const float* adj   = (const float*)d_in[3];
    const float* lapl  = (const float*)d_in[4];
    const float* qW1 = (const float*)d_in[5];  const float* qb1 = (const float*)d_in[6];
    const float* qg  = (const float*)d_in[7];  const float* qbt = (const float*)d_in[8];
    const float* qW2 = (const float*)d_in[9];  const float* qb2 = (const float*)d_in[10];
    const float* dW1 = (const float*)d_in[11]; const float* db1 = (const float*)d_in[12];
    const float* dg  = (const float*)d_in[13]; const float* dbt = (const float*)d_in[14];
    const float* dW2 = (const float*)d_in[15]; const float* db2 = (const float*)d_in[16];
    const float* gatW = (const float*)d_in[17];
    const float* a1   = (const float*)d_in[18];
    const float* a2   = (const float*)d_in[19];
    const float* ln_g = (const float*)d_in[20];
    const float* ln_b = (const float*)d_in[21];
    const float* poW  = (const float*)d_in[22];
    const float* pob  = (const float*)d_in[23];
    float* out = (float*)d_out;

    float *px, *pWh, *phcat, *pG, *pLG, *pt1, *pq, *pp, *pS;
    cudaGetSymbolAddress((void**)&px,    g_x);
    cudaGetSymbolAddress((void**)&pWh,   g_Wh);
    cudaGetSymbolAddress((void**)&phcat, g_hcat);
    cudaGetSymbolAddress((void**)&pG,    g_G);
    cudaGetSymbolAddress((void**)&pLG,   g_LG);
    cudaGetSymbolAddress((void**)&pt1,   g_t1);
    cudaGetSymbolAddress((void**)&pq,    g_q);
    cudaGetSymbolAddress((void**)&pp,    g_p);
    cudaGetSymbolAddress((void**)&pS,    g_S);

    zero_acc_kernel<<<1, 1>>>();
    compact_adj_kernel<<<NN, 256>>>(adj);
    copy_kernel<<<2048, 512>>>(node, px, NN * GH);

    // ---- GNN layers ----
    for (int l = 0; l < NL_; l++) {
        // Wh[h] = x @ gatW[l,h]   (batched over 8 heads)
        mma_gemm<false><<<dim3(HD_ / 128, NN / 128, NH_), 256>>>(
            px, gatW + (long)l * NH_ * ED * HD_, nullptr, pWh,
            NN, HD_, GH, 0L, (long)ED * HD_, (long)NN * HD_);
        s12_kernel<<<(NH_ * NN * 32 + 255) / 256, 256>>>(a1 + l * NH_ * HD_, a2 + l * NH_ * HD_);
        gat_attn_kernel<<<dim3(NN, NH_), 128>>>();
        ln_elu_res_kernel<<<NN, 256>>>(phcat, ln_g + l * GH, ln_b + l * GH, px);
    }

    // graph_embeds = x @ poW + pob
    mma_gemm<false><<<dim3(ED / 128, NN / 128, 1), 256>>>(px, poW, pob, pG, NN, ED, GH, 0L, 0L, 0L);
    // LG = laplacian @ G
    mma_gemm<false><<<dim3(ED / 128, NN / 128, 1), 256>>>(lapl, pG, nullptr, pLG, NN, ED, NN, 0L, 0L, 0L);
    lapdot_kernel<<<2048, 256>>>();

    // ---- query MLP ----
    mma_gemm<false><<<dim3(ED / 128, BB / 128, 1), 256>>>(query, qW1, qb1, pt1, BB, ED, ED, 0L, 0L, 0L);
    ln_gelu_kernel<<<BB, 256>>>(pt1, qg, qbt);
    mma_gemm<false><<<dim3(ED / 128, BB / 128, 1), 256>>>(pt1, qW2, qb2, pq, BB, ED, ED, 0L, 0L, 0L);
    l2norm_kernel<<<BB, 256>>>(pq);

    // ---- doc MLP ----
    mma_gemm<false><<<dim3(ED / 128, BB / 128, 1), 256>>>(doc, dW1, db1, pt1, BB, ED, ED, 0L, 0L, 0L);
    ln_gelu_kernel<<<BB, 256>>>(pt1, dg, dbt);
    mma_gemm<false><<<dim3(ED / 128, BB / 128, 1), 256>>>(pt1, dW2, db2, pp, BB, ED, ED, 0L, 0L, 0L);
    l2norm_kernel<<<BB, 256>>>(pp);

    // ---- similarities + losses ----
    mma_gemm<true><<<dim3(BB / 128, BB / 128, 1), 256>>>(pq, pp, nullptr, pS, BB, BB, ED, 0L, 0L, 0L);
    infonce_kernel<<<BB, 256>>>();

    finalize_kernel<<<1, 1>>>(out, out_size);
}

// round 9
// speedup vs baseline: 1.6662x; 1.0746x over previous
#include <cuda_runtime.h>
#include <math.h>
#include <stdint.h>

#define ED   1024
#define GH   1024
#define NL_  3
#define NH_  8
#define HD_  128
#define NN   2048
#define BB   1024
#define INV_TEMP 20.0f
#define LAPW 0.1
#define MAXD 2048

// ---------------- scratch (static device memory; no allocations) ----------------
__device__ float g_x[NN * GH];            // GNN node features (residual stream)
__device__ float g_Wh[NH_ * NN * HD_];    // per-head projected features
__device__ float g_s1[NH_ * NN];
__device__ float g_s2[NH_ * NN];
__device__ float g_hcat[NN * GH];         // concat-head GAT output (pre LN)
__device__ float g_G[NN * ED];            // graph_embeds
__device__ float g_LG[NN * ED];           // laplacian @ graph_embeds
__device__ float g_t1[2 * BB * ED];       // MLP hidden (q | d)
__device__ float g_qp[2 * BB * ED];       // q | p (contiguous for S gemm)
__device__ float g_S[BB * BB];            // q @ p^T (unscaled)
__device__ int   g_ncnt[NN];
__device__ int   g_nidx[NN * MAXD];
__device__ double g_acc[2];               // [0]=info_nce sum, [1]=lap sum

// ---------------- utility kernels ----------------
__global__ void zero_acc_kernel() { g_acc[0] = 0.0; g_acc[1] = 0.0; }

__global__ void copy_kernel(const float* __restrict__ src, float* __restrict__ dst, int n) {
    int i = blockIdx.x * blockDim.x + threadIdx.x;
    int stride = gridDim.x * blockDim.x;
    for (; i < n; i += stride) dst[i] = src[i];
}

// ---------------- batched pointer pack for GEMM ----------------
struct Ptrs { const float* A; const float* B; const float* bias; float* C; };
struct Batch { Ptrs p[8]; };

// RNE round to tf32, result as raw bits (numerics identical to cvt-in-fragment R3 path)
__device__ __forceinline__ uint32_t f2tf(float f) {
    uint32_t u;
    asm volatile("cvt.rna.tf32.f32 %0, %1;" : "=r"(u) : "f"(f));
    return u;
}

#define MMA_TF32(c0,c1,c2,c3, a0,a1,a2,a3, b0,b1)                                   \
    asm volatile("mma.sync.aligned.m16n8k8.row.col.f32.tf32.tf32.f32 "              \
        "{%0,%1,%2,%3}, {%4,%5,%6,%7}, {%8,%9}, {%0,%1,%2,%3};"                     \
        : "+f"(c0), "+f"(c1), "+f"(c2), "+f"(c3)                                    \
        : "r"(a0), "r"(a1), "r"(a2), "r"(a3), "r"(b0), "r"(b1))

// ---------------- tensor-core GEMM: C[M,N] = A[M,K] @ op(B) (+bias) ----------------
// BM=128, BN=128, BK=16; 256 threads = 8 warps (2m x 4n), warp tile 64x32.
// Data converted to tf32 (RNE) ONCE per element at tile-store time; fragments
// read raw bits. Double-buffered via registers, one __syncthreads per tile.
// TRANSB=false: B row-major [K,N]; TRANSB=true: B row-major [N,K] (C = A @ B^T).
// Requires M%128==0, N%128==0, K%16==0. Per-z pointers from Batch.
template <bool TRANSB>
__global__ void __launch_bounds__(256, 2)
mma_gemm(Batch bt, int M, int N, int K) {
    const Ptrs pz = bt.p[blockIdx.z];
    const float* __restrict__ A    = pz.A;
    const float* __restrict__ B    = pz.B;
    const float* __restrict__ bias = pz.bias;
    float* __restrict__ C          = pz.C;

    __shared__ __align__(16) float As[2][128][20];
    __shared__ __align__(16) float Bs[2 * 2560];

    const int tid  = threadIdx.x;
    const int lane = tid & 31;
    const int w    = tid >> 5;
    const int wm   = (w >> 2) * 64;  // 0 or 64
    const int wn   = (w & 3) * 32;   // 0,32,64,96
    const int g    = lane >> 2;      // 0..7
    const int tq   = lane & 3;       // 0..3

    const int row0 = blockIdx.y * 128;
    const int col0 = blockIdx.x * 128;

    // per-thread tile staging registers
    float4 ra[2], rb[2];
    // A-chunk indexing: i = c*256+tid -> row i>>2, k (i&3)*4
    const int a_r0 = tid >> 2, a_k0 = (tid & 3) << 2;           // c=0
    const int a_r1 = (256 + tid) >> 2, a_k1 = a_k0;             // c=1
    // B !TRANSB: i -> k-row i>>5, n (i&31)*4 ; TRANSB: same as A
    const int bn_r0 = tid >> 5, bn_n0 = (tid & 31) << 2;
    const int bn_r1 = (256 + tid) >> 5, bn_n1 = bn_n0;

    auto load_regs = [&](int t) {
        const int k0 = t << 4;
        ra[0] = *(const float4*)(A + (long)(row0 + a_r0) * K + k0 + a_k0);
        ra[1] = *(const float4*)(A + (long)(row0 + a_r1) * K + k0 + a_k1);
        if (!TRANSB) {
            rb[0] = *(const float4*)(B + (long)(k0 + bn_r0) * N + col0 + bn_n0);
            rb[1] = *(const float4*)(B + (long)(k0 + bn_r1) * N + col0 + bn_n1);
        } else {
            rb[0] = *(const float4*)(B + (long)(col0 + a_r0) * K + k0 + a_k0);
            rb[1] = *(const float4*)(B + (long)(col0 + a_r1) * K + k0 + a_k1);
        }
    };

    auto cvt4 = [&](float4 v) {
        uint4 u;
        u.x = f2tf(v.x); u.y = f2tf(v.y); u.z = f2tf(v.z); u.w = f2tf(v.w);
        return u;
    };

    auto store_smem = [&](int buf) {
        *(uint4*)&As[buf][a_r0][a_k0] = cvt4(ra[0]);
        *(uint4*)&As[buf][a_r1][a_k1] = cvt4(ra[1]);
        if (!TRANSB) {
            *(uint4*)&Bs[buf * 2560 + bn_r0 * 136 + bn_n0] = cvt4(rb[0]);
            *(uint4*)&Bs[buf * 2560 + bn_r1 * 136 + bn_n1] = cvt4(rb[1]);
        } else {
            *(uint4*)&Bs[buf * 2560 + a_r0 * 20 + a_k0] = cvt4(rb[0]);
            *(uint4*)&Bs[buf * 2560 + a_r1 * 20 + a_k1] = cvt4(rb[1]);
        }
    };

    float acc[4][4][4];
    #pragma unroll
    for (int mi = 0; mi < 4; mi++)
        #pragma unroll
        for (int ni = 0; ni < 4; ni++)
            #pragma unroll
            for (int e = 0; e < 4; e++) acc[mi][ni][e] = 0.f;

    const int tiles = K >> 4;

    load_regs(0);
    store_smem(0);
    __syncthreads();

    int buf = 0;
    for (int t = 0; t < tiles; t++) {
        if (t + 1 < tiles) load_regs(t + 1);   // LDGs in flight under the MMA loop

        #pragma unroll
        for (int kk = 0; kk < 2; kk++) {
            const int kb = kk * 8;
            uint32_t af[4][4];
            #pragma unroll
            for (int mi = 0; mi < 4; mi++) {
                const float* ap = &As[buf][wm + mi * 16][0];
                af[mi][0] = __float_as_uint(ap[(g)     * 20 + kb + tq]);
                af[mi][1] = __float_as_uint(ap[(g + 8) * 20 + kb + tq]);
                af[mi][2] = __float_as_uint(ap[(g)     * 20 + kb + tq + 4]);
                af[mi][3] = __float_as_uint(ap[(g + 8) * 20 + kb + tq + 4]);
            }
            uint32_t bfr[4][2];
            #pragma unroll
            for (int ni = 0; ni < 4; ni++) {
                int col = wn + ni * 8 + g;
                if (!TRANSB) {
                    bfr[ni][0] = __float_as_uint(Bs[buf * 2560 + (kb + tq)     * 136 + col]);
                    bfr[ni][1] = __float_as_uint(Bs[buf * 2560 + (kb + tq + 4) * 136 + col]);
                } else {
                    bfr[ni][0] = __float_as_uint(Bs[buf * 2560 + col * 20 + kb + tq]);
                    bfr[ni][1] = __float_as_uint(Bs[buf * 2560 + col * 20 + kb + tq + 4]);
                }
            }
            #pragma unroll
            for (int mi = 0; mi < 4; mi++)
                #pragma unroll
                for (int ni = 0; ni < 4; ni++)
                    MMA_TF32(acc[mi][ni][0], acc[mi][ni][1], acc[mi][ni][2], acc[mi][ni][3],
                             af[mi][0], af[mi][1], af[mi][2], af[mi][3],
                             bfr[ni][0], bfr[ni][1]);
        }

        if (t + 1 < tiles) store_smem(buf ^ 1);  // write other buffer; no WAR on buf
        __syncthreads();
        buf ^= 1;
    }

    // epilogue
    #pragma unroll
    for (int mi = 0; mi < 4; mi++) {
        int r0 = row0 + wm + mi * 16 + g;
        #pragma unroll
        for (int ni = 0; ni < 4; ni++) {
            int cb = col0 + wn + ni * 8 + 2 * tq;
            float b0 = bias ? bias[cb]     : 0.f;
            float b1 = bias ? bias[cb + 1] : 0.f;
            float2 v0 = make_float2(acc[mi][ni][0] + b0, acc[mi][ni][1] + b1);
            float2 v1 = make_float2(acc[mi][ni][2] + b0, acc[mi][ni][3] + b1);
            *(float2*)(C + (long)r0 * N + cb)       = v0;
            *(float2*)(C + (long)(r0 + 8) * N + cb) = v1;
        }
    }
}

// ---------------- adjacency compaction (once per call, reused 24x) ----------------
__global__ void compact_adj_kernel(const float* __restrict__ adj) {
    const int n = blockIdx.x;
    __shared__ int cnt;
    if (threadIdx.x == 0) cnt = 0;
    __syncthreads();
    const float* row = adj + (long)n * NN;
    for (int m = threadIdx.x; m < NN; m += blockDim.x)
        if (row[m] > 0.f) { int p = atomicAdd(&cnt, 1); g_nidx[(long)n * MAXD + p] = m; }
    __syncthreads();
    if (threadIdx.x == 0) g_ncnt[n] = cnt;
}

// ---------------- GAT: s1/s2 scores (one warp per (h,n)) ----------------
__global__ void s12_kernel(const float* __restrict__ a1, const float* __restrict__ a2) {
    int warp = (blockIdx.x * blockDim.x + threadIdx.x) >> 5;
    int lane = threadIdx.x & 31;
    if (warp >= NH_ * NN) return;
    int h = warp / NN;
    const float* w = g_Wh + (long)warp * HD_;
    const float* A1 = a1 + h * HD_;
    const float* A2 = a2 + h * HD_;
    float d1 = 0.f, d2 = 0.f;
    #pragma unroll
    for (int i = lane; i < HD_; i += 32) { float v = w[i]; d1 += v * A1[i]; d2 += v * A2[i]; }
    #pragma unroll
    for (int o = 16; o > 0; o >>= 1) {
        d1 += __shfl_down_sync(0xffffffffu, d1, o);
        d2 += __shfl_down_sync(0xffffffffu, d2, o);
    }
    if (lane == 0) { g_s1[warp] = d1; g_s2[warp] = d2; }
}

// ---------------- GAT attention: sparse softmax + gather (block = (n, h), 128 thr) ----------------
__global__ void gat_attn_kernel() {
    const int n = blockIdx.x, h = blockIdx.y;
    const int tid = threadIdx.x;  // 128
    const int c = g_ncnt[n];
    const int* gidx = g_nidx + (long)n * MAXD;

    __shared__ float sc[MAXD];
    __shared__ int   sidx[MAXD];
    __shared__ float red[128];

    const float s1n = g_s1[h * NN + n];
    const float* s2h = g_s2 + h * NN;

    float mx = -1e30f;
    for (int j = tid; j < c; j += 128) {
        int m = gidx[j];
        sidx[j] = m;
        float e = s1n + s2h[m];
        e = e > 0.f ? e : 0.2f * e;           // leaky_relu(0.2)
        sc[j] = e;
        mx = fmaxf(mx, e);
    }
    red[tid] = mx; __syncthreads();
    for (int o = 64; o > 0; o >>= 1) { if (tid < o) red[tid] = fmaxf(red[tid], red[tid + o]); __syncthreads(); }
    mx = red[0];
    __syncthreads();

    float sm = 0.f;
    for (int j = tid; j < c; j += 128) { float e = expf(sc[j] - mx); sc[j] = e; sm += e; }
    red[tid] = sm; __syncthreads();
    for (int o = 64; o > 0; o >>= 1) { if (tid < o) red[tid] += red[tid + o]; __syncthreads(); }
    const float inv = 1.f / red[0];
    __syncthreads();

    // output feature dim = tid (HD_ == 128)
    float acc = 0.f;
    const float* whh = g_Wh + (long)h * NN * HD_;
    #pragma unroll 4
    for (int j = 0; j < c; j++)
        acc += sc[j] * whh[(long)sidx[j] * HD_ + tid];
    g_hcat[(long)n * GH + h * HD_ + tid] = acc * inv;
}

// ---------------- row-wise LN (+activation) kernels, row width 1024, 256 thr ----------------
// grid = 2*BB rows over g_t1; batch 0 uses (g0,b0), batch 1 uses (g1,b1)
__global__ void ln_gelu2_kernel(float* __restrict__ x,
                                const float* __restrict__ g0, const float* __restrict__ b0,
                                const float* __restrict__ g1, const float* __restrict__ b1) {
    const int row = blockIdx.x, tid = threadIdx.x;
    const float* g = (row < BB) ? g0 : g1;
    const float* b = (row < BB) ? b0 : b1;
    float* xr = x + (long)row * 1024;
    float v[4]; float s = 0.f, ss = 0.f;
    #pragma unroll
    for (int i = 0; i < 4; i++) { v[i] = xr[tid + i * 256]; s += v[i]; ss += v[i] * v[i]; }
    __shared__ float rs[256], rss[256];
    rs[tid] = s; rss[tid] = ss; __syncthreads();
    for (int o = 128; o > 0; o >>= 1) { if (tid < o) { rs[tid] += rs[tid + o]; rss[tid] += rss[tid + o]; } __syncthreads(); }
    float mean = rs[0] * (1.f / 1024.f);
    float var  = rss[0] * (1.f / 1024.f) - mean * mean;
    float rstd = rsqrtf(var + 1e-5f);
    #pragma unroll
    for (int i = 0; i < 4; i++) {
        int cidx = tid + i * 256;
        float t = (v[i] - mean) * rstd * g[cidx] + b[cidx];
        xr[cidx] = 0.5f * t * (1.f + erff(t * 0.70710678118654752f));  // exact gelu
    }
}

__global__ void ln_elu_res_kernel(const float* __restrict__ hin, const float* __restrict__ g,
                                  const float* __restrict__ b, float* __restrict__ x) {
    const int row = blockIdx.x, tid = threadIdx.x;
    const float* hr = hin + (long)row * 1024;
    float* xr = x + (long)row * 1024;
    float v[4]; float s = 0.f, ss = 0.f;
    #pragma unroll
    for (int i = 0; i < 4; i++) { v[i] = hr[tid + i * 256]; s += v[i]; ss += v[i] * v[i]; }
    __shared__ float rs[256], rss[256];
    rs[tid] = s; rss[tid] = ss; __syncthreads();
    for (int o = 128; o > 0; o >>= 1) { if (tid < o) { rs[tid] += rs[tid + o]; rss[tid] += rss[tid + o]; } __syncthreads(); }
    float mean = rs[0] * (1.f / 1024.f);
    float var  = rss[0] * (1.f / 1024.f) - mean * mean;
    float rstd = rsqrtf(var + 1e-5f);
    #pragma unroll
    for (int i = 0; i < 4; i++) {
        int cidx = tid + i * 256;
        float t = (v[i] - mean) * rstd * g[cidx] + b[cidx];
        t = t > 0.f ? t : expm1f(t);          // elu
        xr[cidx] += t;                        // residual
    }
}

__global__ void l2norm_kernel(float* __restrict__ x) {
    const int row = blockIdx.x, tid = threadIdx.x;
    float* xr = x + (long)row * 1024;
    float v[4]; float ss = 0.f;
    #pragma unroll
    for (int i = 0; i < 4; i++) { v[i] = xr[tid + i * 256]; ss += v[i] * v[i]; }
    __shared__ float rss[256];
    rss[tid] = ss; __syncthreads();
    for (int o = 128; o > 0; o >>= 1) { if (tid < o) rss[tid] += rss[tid + o]; __syncthreads(); }
    float nrm = sqrtf(rss[0]);
    float inv = 1.f / fmaxf(nrm, 1e-12f);
    #pragma unroll
    for (int i = 0; i < 4; i++) xr[tid + i * 256] = v[i] * inv;
}

// ---------------- InfoNCE: per-row logsumexp over [pos, row] ----------------
__global__ void infonce_kernel() {
    const int i = blockIdx.x, tid = threadIdx.x;  // 256 thr, BB rows
    const float* row = g_S + (long)i * BB;
    const float pos = row[i] * INV_TEMP;

    __shared__ float red[256];
    float mx = -1e30f;
    for (int j = tid; j < BB; j += 256) mx = fmaxf(mx, row[j] * INV_TEMP);
    red[tid] = mx; __syncthreads();
    for (int o = 128; o > 0; o >>= 1) { if (tid < o) red[tid] = fmaxf(red[tid], red[tid + o]); __syncthreads(); }
    mx = red[0];
    __syncthreads();

    float sm = 0.f;
    for (int j = tid; j < BB; j += 256) sm += expf(row[j] * INV_TEMP - mx);
    red[tid] = sm; __syncthreads();
    for (int o = 128; o > 0; o >>= 1) { if (tid < o) red[tid] += red[tid + o]; __syncthreads(); }

    if (tid == 0) {
        float total = red[0] + expf(pos - mx);   // duplicate pos logit (concat)
        float loss = logf(total) + mx - pos;
        atomicAdd(&g_acc[0], (double)loss);
    }
}

// ---------------- Laplacian regularizer: sum(G * LG) ----------------
__global__ void lapdot_kernel() {
    const int n = NN * ED;
    double local = 0.0;
    for (int i = blockIdx.x * blockDim.x + threadIdx.x; i < n; i += gridDim.x * blockDim.x)
        local += (double)g_G[i] * (double)g_LG[i];
    __shared__ double rd[256];
    rd[threadIdx.x] = local; __syncthreads();
    for (int o = 128; o > 0; o >>= 1) { if (threadIdx.x < o) rd[threadIdx.x] += rd[threadIdx.x + o]; __syncthreads(); }
    if (threadIdx.x == 0) atomicAdd(&g_acc[1], rd[0]);
}

__global__ void finalize_kernel(float* out, int out_size) {
    double info = g_acc[0] / (double)BB;
    double lap  = g_acc[1] / (double)NN;
    double vals[3] = { info + LAPW * lap, info, lap };
    for (int i = 0; i < out_size && i < 3; i++) out[i] = (float)vals[i];
}

// ---------------- launch ----------------
extern "C" void kernel_launch(void* const* d_in, const int* in_sizes, int n_in,
                              void* d_out, int out_size) {
    const float* query = (const float*)d_in[0];
    const float* doc   = (const float*)d_in[1];
    const float* node  = (const float*)d_in[2];
    const float* adj   = (const float*)d_in[3];
    const float* lapl  = (const float*)d_in[4];
    const float* qW1 = (const float*)d_in[5];  const float* qb1 = (const float*)d_in[6];
    const float* qg  = (const float*)d_in[7];  const float* qbt = (const float*)d_in[8];
    const float* qW2 = (const float*)d_in[9];  const float* qb2 = (const float*)d_in[10];
    const float* dW1 = (const float*)d_in[11]; const float* db1 = (const float*)d_in[12];
    const float* dg  = (const float*)d_in[13]; const float* dbt = (const float*)d_in[14];
    const float* dW2 = (const float*)d_in[15]; const float* db2 = (const float*)d_in[16];
    const float* gatW = (const float*)d_in[17];
    const float* a1   = (const float*)d_in[18];
    const float* a2   = (const float*)d_in[19];
    const float* ln_g = (const float*)d_in[20];
    const float* ln_b = (const float*)d_in[21];
    const float* poW  = (const float*)d_in[22];
    const float* pob  = (const float*)d_in[23];
    float* out = (float*)d_out;

    float *px, *pWh, *phcat, *pG, *pLG, *pt1, *pqp, *pS;
    cudaGetSymbolAddress((void**)&px,    g_x);
    cudaGetSymbolAddress((void**)&pWh,   g_Wh);
    cudaGetSymbolAddress((void**)&phcat, g_hcat);
    cudaGetSymbolAddress((void**)&pG,    g_G);
    cudaGetSymbolAddress((void**)&pLG,   g_LG);
    cudaGetSymbolAddress((void**)&pt1,   g_t1);
    cudaGetSymbolAddress((void**)&pqp,   g_qp);
    cudaGetSymbolAddress((void**)&pS,    g_S);

    const long QO = (long)BB * ED;   // batch offset

    zero_acc_kernel<<<1, 1>>>();
    compact_adj_kernel<<<NN, 256>>>(adj);
    copy_kernel<<<2048, 512>>>(node, px, NN * GH);

    // ---- GNN layers ----
    for (int l = 0; l < NL_; l++) {
        Batch bw = {};
        for (int h = 0; h < NH_; h++) {
            bw.p[h].A = px;
            bw.p[h].B = gatW + (long)l * NH_ * ED * HD_ + (long)h * ED * HD_;
            bw.p[h].bias = nullptr;
            bw.p[h].C = pWh + (long)h * NN * HD_;
        }
        mma_gemm<false><<<dim3(HD_ / 128, NN / 128, NH_), 256>>>(bw, NN, HD_, GH);
        s12_kernel<<<(NH_ * NN * 32 + 255) / 256, 256>>>(a1 + l * NH_ * HD_, a2 + l * NH_ * HD_);
        gat_attn_kernel<<<dim3(NN, NH_), 128>>>();
        ln_elu_res_kernel<<<NN, 256>>>(phcat, ln_g + l * GH, ln_b + l * GH, px);
    }

    // graph_embeds = x @ poW + pob ; LG = laplacian @ G
    { Batch b = {}; b.p[0] = { px, poW, pob, pG };
      mma_gemm<false><<<dim3(ED / 128, NN / 128, 1), 256>>>(b, NN, ED, GH); }
    { Batch b = {}; b.p[0] = { lapl, pG, nullptr, pLG };
      mma_gemm<false><<<dim3(ED / 128, NN / 128, 1), 256>>>(b, NN, ED, NN); }
    lapdot_kernel<<<2048, 256>>>();

    // ---- q + doc MLPs, batched z=2 ----
    { Batch b = {};
      b.p[0] = { query, qW1, qb1, pt1 };
      b.p[1] = { doc,   dW1, db1, pt1 + QO };
      mma_gemm<false><<<dim3(ED / 128, BB / 128, 2), 256>>>(b, BB, ED, ED); }
    ln_gelu2_kernel<<<2 * BB, 256>>>(pt1, qg, qbt, dg, dbt);
    { Batch b = {};
      b.p[0] = { pt1,      qW2, qb2, pqp };
      b.p[1] = { pt1 + QO, dW2, db2, pqp + QO };
      mma_gemm<false><<<dim3(ED / 128, BB / 128, 2), 256>>>(b, BB, ED, ED); }
    l2norm_kernel<<<2 * BB, 256>>>(pqp);

    // ---- similarities + losses ----
    { Batch b = {}; b.p[0] = { pqp, pqp + QO, nullptr, pS };
      mma_gemm<true><<<dim3(BB / 128, BB / 128, 1), 256>>>(b, BB, BB, ED); }
    infonce_kernel<<<BB, 256>>>();

    finalize_kernel<<<1, 1>>>(out, out_size);
}

// round 10
// speedup vs baseline: 2.3742x; 1.4250x over previous
#include <cuda_runtime.h>
#include <math.h>
#include <stdint.h>

#define ED   1024
#define GH   1024
#define NL_  3
#define NH_  8
#define HD_  128
#define NN   2048
#define BB   1024
#define INV_TEMP 20.0f
#define LAPW 0.1
#define MAXD 2048

// ---------------- scratch (static device memory; no allocations) ----------------
__device__ float g_x[NN * GH];            // GNN node features (residual stream)
__device__ float g_Wh[NH_ * NN * HD_];    // per-head projected features
__device__ float g_s1[NH_ * NN];
__device__ float g_s2[NH_ * NN];
__device__ float g_hcat[NN * GH];         // concat-head GAT output (pre LN)
__device__ float g_G[NN * ED];            // graph_embeds
__device__ float g_LG[NN * ED];           // laplacian @ graph_embeds
__device__ float g_t1[2 * BB * ED];       // MLP hidden (q | d)
__device__ float g_qp[2 * BB * ED];       // q | p (contiguous for S gemm)
__device__ float g_S[BB * BB];            // q @ p^T (unscaled)
__device__ int   g_ncnt[NN];
__device__ int   g_nidx[NN * MAXD];
__device__ double g_acc[2];               // [0]=info_nce sum, [1]=lap sum

// ---------------- utility kernels ----------------
__global__ void zero_acc_kernel() { g_acc[0] = 0.0; g_acc[1] = 0.0; }

__global__ void copy_kernel(const float* __restrict__ src, float* __restrict__ dst, int n) {
    int i = blockIdx.x * blockDim.x + threadIdx.x;
    int stride = gridDim.x * blockDim.x;
    for (; i < n; i += stride) dst[i] = src[i];
}

// ---------------- batched pointer pack for GEMM ----------------
struct Ptrs { const float* A; const float* B; const float* bias; float* C; };
struct Batch { Ptrs p[8]; };

// RNE round to tf32, result as raw bits
__device__ __forceinline__ uint32_t f2tf(float f) {
    uint32_t u;
    asm volatile("cvt.rna.tf32.f32 %0, %1;" : "=r"(u) : "f"(f));
    return u;
}

#define MMA_TF32(c0,c1,c2,c3, a0,a1,a2,a3, b0,b1)                                   \
    asm volatile("mma.sync.aligned.m16n8k8.row.col.f32.tf32.tf32.f32 "              \
        "{%0,%1,%2,%3}, {%4,%5,%6,%7}, {%8,%9}, {%0,%1,%2,%3};"                     \
        : "+f"(c0), "+f"(c1), "+f"(c2), "+f"(c3)                                    \
        : "r"(a0), "r"(a1), "r"(a2), "r"(a3), "r"(b0), "r"(b1))

// ---------------- tensor-core GEMM: C[M,N] = A[M,K] @ op(B) (+bias) ----------------
// BM=64, BN=128, BK=16; 256 threads = 8 warps (2m x 4n), warp tile 32x32.
// Grid is 2x finer in M than the old 128x128 tile -> >=148 blocks on all big GEMMs.
// tf32 (RNE) conversion once per element at tile-store; fragments read raw bits.
// Double-buffered via registers, one __syncthreads per tile.
// TRANSB=false: B row-major [K,N]; TRANSB=true: B row-major [N,K] (C = A @ B^T).
// Requires M%64==0, N%128==0, K%16==0. Per-z pointers from Batch.
template <bool TRANSB>
__global__ void __launch_bounds__(256, 2)
mma_gemm(Batch bt, int M, int N, int K) {
    const Ptrs pz = bt.p[blockIdx.z];
    const float* __restrict__ A    = pz.A;
    const float* __restrict__ B    = pz.B;
    const float* __restrict__ bias = pz.bias;
    float* __restrict__ C          = pz.C;

    __shared__ __align__(16) float As[2][64][20];
    __shared__ __align__(16) float Bs[2 * 2560];

    const int tid  = threadIdx.x;
    const int lane = tid & 31;
    const int w    = tid >> 5;
    const int wm   = (w >> 2) * 32;  // 0 or 32
    const int wn   = (w & 3) * 32;   // 0,32,64,96
    const int g    = lane >> 2;      // 0..7
    const int tq   = lane & 3;       // 0..3

    const int row0 = blockIdx.y * 64;
    const int col0 = blockIdx.x * 128;

    // per-thread tile staging registers
    float4 ra, rb[2];
    // A: 64x16 = 256 float4 chunks, 1/thread: row tid>>2, k (tid&3)*4
    const int a_r = tid >> 2, a_k = (tid & 3) << 2;
    // B !TRANSB: 16x128 = 512 float4, 2/thread: i=c*256+tid -> k-row i>>5, n (i&31)*4
    const int bn_r0 = tid >> 5,        bn_n0 = (tid & 31) << 2;
    const int bn_r1 = (256 + tid) >> 5, bn_n1 = bn_n0;
    // B TRANSB: 128 n-rows x 16 k = 512 float4, 2/thread: n-row i>>2, k (i&3)*4
    const int bt_r0 = tid >> 2,        bt_k0 = (tid & 3) << 2;
    const int bt_r1 = (256 + tid) >> 2, bt_k1 = bt_k0;

    auto load_regs = [&](int t) {
        const int k0 = t << 4;
        ra = *(const float4*)(A + (long)(row0 + a_r) * K + k0 + a_k);
        if (!TRANSB) {
            rb[0] = *(const float4*)(B + (long)(k0 + bn_r0) * N + col0 + bn_n0);
            rb[1] = *(const float4*)(B + (long)(k0 + bn_r1) * N + col0 + bn_n1);
        } else {
            rb[0] = *(const float4*)(B + (long)(col0 + bt_r0) * K + k0 + bt_k0);
            rb[1] = *(const float4*)(B + (long)(col0 + bt_r1) * K + k0 + bt_k1);
        }
    };

    auto cvt4 = [&](float4 v) {
        uint4 u;
        u.x = f2tf(v.x); u.y = f2tf(v.y); u.z = f2tf(v.z); u.w = f2tf(v.w);
        return u;
    };

    auto store_smem = [&](int buf) {
        *(uint4*)&As[buf][a_r][a_k] = cvt4(ra);
        if (!TRANSB) {
            *(uint4*)&Bs[buf * 2560 + bn_r0 * 136 + bn_n0] = cvt4(rb[0]);
            *(uint4*)&Bs[buf * 2560 + bn_r1 * 136 + bn_n1] = cvt4(rb[1]);
        } else {
            *(uint4*)&Bs[buf * 2560 + bt_r0 * 20 + bt_k0] = cvt4(rb[0]);
            *(uint4*)&Bs[buf * 2560 + bt_r1 * 20 + bt_k1] = cvt4(rb[1]);
        }
    };

    float acc[2][4][4];
    #pragma unroll
    for (int mi = 0; mi < 2; mi++)
        #pragma unroll
        for (int ni = 0; ni < 4; ni++)
            #pragma unroll
            for (int e = 0; e < 4; e++) acc[mi][ni][e] = 0.f;

    const int tiles = K >> 4;

    load_regs(0);
    store_smem(0);
    __syncthreads();

    int buf = 0;
    for (int t = 0; t < tiles; t++) {
        if (t + 1 < tiles) load_regs(t + 1);   // LDGs in flight under the MMA loop

        #pragma unroll
        for (int kk = 0; kk < 2; kk++) {
            const int kb = kk * 8;
            uint32_t af[2][4];
            #pragma unroll
            for (int mi = 0; mi < 2; mi++) {
                const float* ap = &As[buf][wm + mi * 16][0];
                af[mi][0] = __float_as_uint(ap[(g)     * 20 + kb + tq]);
                af[mi][1] = __float_as_uint(ap[(g + 8) * 20 + kb + tq]);
                af[mi][2] = __float_as_uint(ap[(g)     * 20 + kb + tq + 4]);
                af[mi][3] = __float_as_uint(ap[(g + 8) * 20 + kb + tq + 4]);
            }
            uint32_t bfr[4][2];
            #pragma unroll
            for (int ni = 0; ni < 4; ni++) {
                int col = wn + ni * 8 + g;
                if (!TRANSB) {
                    bfr[ni][0] = __float_as_uint(Bs[buf * 2560 + (kb + tq)     * 136 + col]);
                    bfr[ni][1] = __float_as_uint(Bs[buf * 2560 + (kb + tq + 4) * 136 + col]);
                } else {
                    bfr[ni][0] = __float_as_uint(Bs[buf * 2560 + col * 20 + kb + tq]);
                    bfr[ni][1] = __float_as_uint(Bs[buf * 2560 + col * 20 + kb + tq + 4]);
                }
            }
            #pragma unroll
            for (int mi = 0; mi < 2; mi++)
                #pragma unroll
                for (int ni = 0; ni < 4; ni++)
                    MMA_TF32(acc[mi][ni][0], acc[mi][ni][1], acc[mi][ni][2], acc[mi][ni][3],
                             af[mi][0], af[mi][1], af[mi][2], af[mi][3],
                             bfr[ni][0], bfr[ni][1]);
        }

        if (t + 1 < tiles) store_smem(buf ^ 1);  // write other buffer; no WAR on buf
        __syncthreads();
        buf ^= 1;
    }

    // epilogue
    #pragma unroll
    for (int mi = 0; mi < 2; mi++) {
        int r0 = row0 + wm + mi * 16 + g;
        #pragma unroll
        for (int ni = 0; ni < 4; ni++) {
            int cb = col0 + wn + ni * 8 + 2 * tq;
            float b0 = bias ? bias[cb]     : 0.f;
            float b1 = bias ? bias[cb + 1] : 0.f;
            float2 v0 = make_float2(acc[mi][ni][0] + b0, acc[mi][ni][1] + b1);
            float2 v1 = make_float2(acc[mi][ni][2] + b0, acc[mi][ni][3] + b1);
            *(float2*)(C + (long)r0 * N + cb)       = v0;
            *(float2*)(C + (long)(r0 + 8) * N + cb) = v1;
        }
    }
}

// ---------------- adjacency compaction (once per call, reused 24x) ----------------
__global__ void compact_adj_kernel(const float* __restrict__ adj) {
    const int n = blockIdx.x;
    __shared__ int cnt;
    if (threadIdx.x == 0) cnt = 0;
    __syncthreads();
    const float* row = adj + (long)n * NN;
    for (int m = threadIdx.x; m < NN; m += blockDim.x)
        if (row[m] > 0.f) { int p = atomicAdd(&cnt, 1); g_nidx[(long)n * MAXD + p] = m; }
    __syncthreads();
    if (threadIdx.x == 0) g_ncnt[n] = cnt;
}

// ---------------- GAT: s1/s2 scores (one warp per (h,n)) ----------------
__global__ void s12_kernel(const float* __restrict__ a1, const float* __restrict__ a2) {
    int warp = (blockIdx.x * blockDim.x + threadIdx.x) >> 5;
    int lane = threadIdx.x & 31;
    if (warp >= NH_ * NN) return;
    int h = warp / NN;
    const float* w = g_Wh + (long)warp * HD_;
    const float* A1 = a1 + h * HD_;
    const float* A2 = a2 + h * HD_;
    float d1 = 0.f, d2 = 0.f;
    #pragma unroll
    for (int i = lane; i < HD_; i += 32) { float v = w[i]; d1 += v * A1[i]; d2 += v * A2[i]; }
    #pragma unroll
    for (int o = 16; o > 0; o >>= 1) {
        d1 += __shfl_down_sync(0xffffffffu, d1, o);
        d2 += __shfl_down_sync(0xffffffffu, d2, o);
    }
    if (lane == 0) { g_s1[warp] = d1; g_s2[warp] = d2; }
}

// ---------------- GAT attention: sparse softmax + gather (block = (n, h), 128 thr) ----------------
__global__ void gat_attn_kernel() {
    const int n = blockIdx.x, h = blockIdx.y;
    const int tid = threadIdx.x;  // 128
    const int c = g_ncnt[n];
    const int* gidx = g_nidx + (long)n * MAXD;

    __shared__ float sc[MAXD];
    __shared__ int   sidx[MAXD];
    __shared__ float red[128];

    const float s1n = g_s1[h * NN + n];
    const float* s2h = g_s2 + h * NN;

    float mx = -1e30f;
    for (int j = tid; j < c; j += 128) {
        int m = gidx[j];
        sidx[j] = m;
        float e = s1n + s2h[m];
        e = e > 0.f ? e : 0.2f * e;           // leaky_relu(0.2)
        sc[j] = e;
        mx = fmaxf(mx, e);
    }
    red[tid] = mx; __syncthreads();
    for (int o = 64; o > 0; o >>= 1) { if (tid < o) red[tid] = fmaxf(red[tid], red[tid + o]); __syncthreads(); }
    mx = red[0];
    __syncthreads();

    float sm = 0.f;
    for (int j = tid; j < c; j += 128) { float e = expf(sc[j] - mx); sc[j] = e; sm += e; }
    red[tid] = sm; __syncthreads();
    for (int o = 64; o > 0; o >>= 1) { if (tid < o) red[tid] += red[tid + o]; __syncthreads(); }
    const float inv = 1.f / red[0];
    __syncthreads();

    // output feature dim = tid (HD_ == 128)
    float acc = 0.f;
    const float* whh = g_Wh + (long)h * NN * HD_;
    #pragma unroll 4
    for (int j = 0; j < c; j++)
        acc += sc[j] * whh[(long)sidx[j] * HD_ + tid];
    g_hcat[(long)n * GH + h * HD_ + tid] = acc * inv;
}

// ---------------- row-wise LN (+activation) kernels, row width 1024, 256 thr ----------------
// grid = 2*BB rows over g_t1; batch 0 uses (g0,b0), batch 1 uses (g1,b1)
__global__ void ln_gelu2_kernel(float* __restrict__ x,
                                const float* __restrict__ g0, const float* __restrict__ b0,
                                const float* __restrict__ g1, const float* __restrict__ b1) {
    const int row = blockIdx.x, tid = threadIdx.x;
    const float* g = (row < BB) ? g0 : g1;
    const float* b = (row < BB) ? b0 : b1;
    float* xr = x + (long)row * 1024;
    float v[4]; float s = 0.f, ss = 0.f;
    #pragma unroll
    for (int i = 0; i < 4; i++) { v[i] = xr[tid + i * 256]; s += v[i]; ss += v[i] * v[i]; }
    __shared__ float rs[256], rss[256];
    rs[tid] = s; rss[tid] = ss; __syncthreads();
    for (int o = 128; o > 0; o >>= 1) { if (tid < o) { rs[tid] += rs[tid + o]; rss[tid] += rss[tid + o]; } __syncthreads(); }
    float mean = rs[0] * (1.f / 1024.f);
    float var  = rss[0] * (1.f / 1024.f) - mean * mean;
    float rstd = rsqrtf(var + 1e-5f);
    #pragma unroll
    for (int i = 0; i < 4; i++) {
        int cidx = tid + i * 256;
        float t = (v[i] - mean) * rstd * g[cidx] + b[cidx];
        xr[cidx] = 0.5f * t * (1.f + erff(t * 0.70710678118654752f));  // exact gelu
    }
}

__global__ void ln_elu_res_kernel(const float* __restrict__ hin, const float* __restrict__ g,
                                  const float* __restrict__ b, float* __restrict__ x) {
    const int row = blockIdx.x, tid = threadIdx.x;
    const float* hr = hin + (long)row * 1024;
    float* xr = x + (long)row * 1024;
    float v[4]; float s = 0.f, ss = 0.f;
    #pragma unroll
    for (int i = 0; i < 4; i++) { v[i] = hr[tid + i * 256]; s += v[i]; ss += v[i] * v[i]; }
    __shared__ float rs[256], rss[256];
    rs[tid] = s; rss[tid] = ss; __syncthreads();
    for (int o = 128; o > 0; o >>= 1) { if (tid < o) { rs[tid] += rs[tid + o]; rss[tid] += rss[tid + o]; } __syncthreads(); }
    float mean = rs[0] * (1.f / 1024.f);
    float var  = rss[0] * (1.f / 1024.f) - mean * mean;
    float rstd = rsqrtf(var + 1e-5f);
    #pragma unroll
    for (int i = 0; i < 4; i++) {
        int cidx = tid + i * 256;
        float t = (v[i] - mean) * rstd * g[cidx] + b[cidx];
        t = t > 0.f ? t : expm1f(t);          // elu
        xr[cidx] += t;                        // residual
    }
}

__global__ void l2norm_kernel(float* __restrict__ x) {
    const int row = blockIdx.x, tid = threadIdx.x;
    float* xr = x + (long)row * 1024;
    float v[4]; float ss = 0.f;
    #pragma unroll
    for (int i = 0; i < 4; i++) { v[i] = xr[tid + i * 256]; ss += v[i] * v[i]; }
    __shared__ float rss[256];
    rss[tid] = ss; __syncthreads();
    for (int o = 128; o > 0; o >>= 1) { if (tid < o) rss[tid] += rss[tid + o]; __syncthreads(); }
    float nrm = sqrtf(rss[0]);
    float inv = 1.f / fmaxf(nrm, 1e-12f);
    #pragma unroll
    for (int i = 0; i < 4; i++) xr[tid + i * 256] = v[i] * inv;
}

// ---------------- InfoNCE: per-row logsumexp over [pos, row] ----------------
__global__ void infonce_kernel() {
    const int i = blockIdx.x, tid = threadIdx.x;  // 256 thr, BB rows
    const float* row = g_S + (long)i * BB;
    const float pos = row[i] * INV_TEMP;

    __shared__ float red[256];
    float mx = -1e30f;
    for (int j = tid; j < BB; j += 256) mx = fmaxf(mx, row[j] * INV_TEMP);
    red[tid] = mx; __syncthreads();
    for (int o = 128; o > 0; o >>= 1) { if (tid < o) red[tid] = fmaxf(red[tid], red[tid + o]); __syncthreads(); }
    mx = red[0];
    __syncthreads();

    float sm = 0.f;
    for (int j = tid; j < BB; j += 256) sm += expf(row[j] * INV_TEMP - mx);
    red[tid] = sm; __syncthreads();
    for (int o = 128; o > 0; o >>= 1) { if (tid < o) red[tid] += red[tid + o]; __syncthreads(); }

    if (tid == 0) {
        float total = red[0] + expf(pos - mx);   // duplicate pos logit (concat)
        float loss = logf(total) + mx - pos;
        atomicAdd(&g_acc[0], (double)loss);
    }
}

// ---------------- Laplacian regularizer: sum(G * LG) ----------------
__global__ void lapdot_kernel() {
    const int n = NN * ED;
    double local = 0.0;
    for (int i = blockIdx.x * blockDim.x + threadIdx.x; i < n; i += gridDim.x * blockDim.x)
        local += (double)g_G[i] * (double)g_LG[i];
    __shared__ double rd[256];
    rd[threadIdx.x] = local; __syncthreads();
    for (int o = 128; o > 0; o >>= 1) { if (threadIdx.x < o) rd[threadIdx.x] += rd[threadIdx.x + o]; __syncthreads(); }
    if (threadIdx.x == 0) atomicAdd(&g_acc[1], rd[0]);
}

__global__ void finalize_kernel(float* out, int out_size) {
    double info = g_acc[0] / (double)BB;
    double lap  = g_acc[1] / (double)NN;
    double vals[3] = { info + LAPW * lap, info, lap };
    for (int i = 0; i < out_size && i < 3; i++) out[i] = (float)vals[i];
}

// ---------------- launch ----------------
extern "C" void kernel_launch(void* const* d_in, const int* in_sizes, int n_in,
                              void* d_out, int out_size) {
    const float* query = (const float*)d_in[0];
    const float* doc   = (const float*)d_in[1];
    const float* node  = (const float*)d_in[2];
    const float* adj   = (const float*)d_in[3];
    const float* lapl  = (const float*)d_in[4];
    const float* qW1 = (const float*)d_in[5];  const float* qb1 = (const float*)d_in[6];
    const float* qg  = (const float*)d_in[7];  const float* qbt = (const float*)d_in[8];
    const float* qW2 = (const float*)d_in[9];  const float* qb2 = (const float*)d_in[10];
    const float* dW1 = (const float*)d_in[11]; const float* db1 = (const float*)d_in[12];
    const float* dg  = (const float*)d_in[13]; const float* dbt = (const float*)d_in[14];
    const float* dW2 = (const float*)d_in[15]; const float* db2 = (const float*)d_in[16];
    const float* gatW = (const float*)d_in[17];
    const float* a1   = (const float*)d_in[18];
    const float* a2   = (const float*)d_in[19];
    const float* ln_g = (const float*)d_in[20];
    const float* ln_b = (const float*)d_in[21];
    const float* poW  = (const float*)d_in[22];
    const float* pob  = (const float*)d_in[23];
    float* out = (float*)d_out;

    float *px, *pWh, *phcat, *pG, *pLG, *pt1, *pqp, *pS;
    cudaGetSymbolAddress((void**)&px,    g_x);
    cudaGetSymbolAddress((void**)&pWh,   g_Wh);
    cudaGetSymbolAddress((void**)&phcat, g_hcat);
    cudaGetSymbolAddress((void**)&pG,    g_G);
    cudaGetSymbolAddress((void**)&pLG,   g_LG);
    cudaGetSymbolAddress((void**)&pt1,   g_t1);
    cudaGetSymbolAddress((void**)&pqp,   g_qp);
    cudaGetSymbolAddress((void**)&pS,    g_S);

    const long QO = (long)BB * ED;   // batch offset

    zero_acc_kernel<<<1, 1>>>();
    compact_adj_kernel<<<NN, 256>>>(adj);
    copy_kernel<<<2048, 512>>>(node, px, NN * GH);

    // ---- GNN layers ----
    for (int l = 0; l < NL_; l++) {
        Batch bw = {};
        for (int h = 0; h < NH_; h++) {
            bw.p[h].A = px;
            bw.p[h].B = gatW + (long)l * NH_ * ED * HD_ + (long)h * ED * HD_;
            bw.p[h].bias = nullptr;
            bw.p[h].C = pWh + (long)h * NN * HD_;
        }
        mma_gemm<false><<<dim3(HD_ / 128, NN / 64, NH_), 256>>>(bw, NN, HD_, GH);
        s12_kernel<<<(NH_ * NN * 32 + 255) / 256, 256>>>(a1 + l * NH_ * HD_, a2 + l * NH_ * HD_);
        gat_attn_kernel<<<dim3(NN, NH_), 128>>>();
        ln_elu_res_kernel<<<NN, 256>>>(phcat, ln_g + l * GH, ln_b + l * GH, px);
    }

    // graph_embeds = x @ poW + pob ; LG = laplacian @ G
    { Batch b = {}; b.p[0] = { px, poW, pob, pG };
      mma_gemm<false><<<dim3(ED / 128, NN / 64, 1), 256>>>(b, NN, ED, GH); }
    { Batch b = {}; b.p[0] = { lapl, pG, nullptr, pLG };
      mma_gemm<false><<<dim3(ED / 128, NN / 64, 1), 256>>>(b, NN, ED, NN); }
    lapdot_kernel<<<2048, 256>>>();

    // ---- q + doc MLPs, batched z=2 ----
    { Batch b = {};
      b.p[0] = { query, qW1, qb1, pt1 };
      b.p[1] = { doc,   dW1, db1, pt1 + QO };
      mma_gemm<false><<<dim3(ED / 128, BB / 64, 2), 256>>>(b, BB, ED, ED); }
    ln_gelu2_kernel<<<2 * BB, 256>>>(pt1, qg, qbt, dg, dbt);
    { Batch b = {};
      b.p[0] = { pt1,      qW2, qb2, pqp };
      b.p[1] = { pt1 + QO, dW2, db2, pqp + QO };
      mma_gemm<false><<<dim3(ED / 128, BB / 64, 2), 256>>>(b, BB, ED, ED); }
    l2norm_kernel<<<2 * BB, 256>>>(pqp);

    // ---- similarities + losses ----
    { Batch b = {}; b.p[0] = { pqp, pqp + QO, nullptr, pS };
      mma_gemm<true><<<dim3(BB / 128, BB / 64, 1), 256>>>(b, BB, BB, ED); }
    infonce_kernel<<<BB, 256>>>();

    finalize_kernel<<<1, 1>>>(out, out_size);
}

// round 14
// speedup vs baseline: 2.4134x; 1.0165x over previous
#include <cuda_runtime.h>
#include <math.h>
#include <stdint.h>

#define ED   1024
#define GH   1024
#define NL_  3
#define NH_  8
#define HD_  128
#define NN   2048
#define BB   1024
#define INV_TEMP 20.0f
#define LAPW 0.1
#define MAXD 2048

// ---------------- scratch (static device memory; no allocations) ----------------
__device__ float g_x[NN * GH];            // GNN node features (residual stream)
__device__ float g_Wh[NH_ * NN * HD_];    // per-head projected features
__device__ float g_s1[NH_ * NN];
__device__ float g_s2[NH_ * NN];
__device__ float g_hcat[NN * GH];         // concat-head GAT output (pre LN)
__device__ float g_G[NN * ED];            // graph_embeds
__device__ float g_LG[NN * ED];           // laplacian @ graph_embeds
__device__ float g_t1[2 * BB * ED];       // MLP hidden (q | d)
__device__ float g_qp[2 * BB * ED];       // q | p (contiguous for S gemm)
__device__ float g_S[BB * BB];            // q @ p^T (unscaled)
__device__ int   g_ncnt[NN];
__device__ int   g_nidx[NN * MAXD];
__device__ double g_acc[2];               // [0]=info_nce sum, [1]=lap sum

// ---------------- utility kernels ----------------
__global__ void zero_acc_kernel() { g_acc[0] = 0.0; g_acc[1] = 0.0; }

__global__ void copy_kernel(const float* __restrict__ src, float* __restrict__ dst, int n) {
    int i = blockIdx.x * blockDim.x + threadIdx.x;
    int stride = gridDim.x * blockDim.x;
    for (; i < n; i += stride) dst[i] = src[i];
}

// ---------------- batched pointer pack for GEMM ----------------
struct Ptrs { const float* A; const float* B; const float* bias; float* C; };
struct Batch { Ptrs p[8]; };

// RNE round to tf32, result as raw bits
__device__ __forceinline__ uint32_t f2tf(float f) {
    uint32_t u;
    asm volatile("cvt.rna.tf32.f32 %0, %1;" : "=r"(u) : "f"(f));
    return u;
}

#define MMA_TF32(c0,c1,c2,c3, a0,a1,a2,a3, b0,b1)                                   \
    asm volatile("mma.sync.aligned.m16n8k8.row.col.f32.tf32.tf32.f32 "              \
        "{%0,%1,%2,%3}, {%4,%5,%6,%7}, {%8,%9}, {%0,%1,%2,%3};"                     \
        : "+f"(c0), "+f"(c1), "+f"(c2), "+f"(c3)                                    \
        : "r"(a0), "r"(a1), "r"(a2), "r"(a3), "r"(b0), "r"(b1))

__device__ __forceinline__ void ldsm4(uint32_t* r, uint32_t saddr) {
    asm volatile("ldmatrix.sync.aligned.m8n8.x4.shared.b16 {%0,%1,%2,%3}, [%4];"
        : "=r"(r[0]), "=r"(r[1]), "=r"(r[2]), "=r"(r[3]) : "r"(saddr));
}

// ---------------- tensor-core GEMM: C[M,N] = A[M,K] @ op(B) (+bias) ----------------
// BM=64, BN=128, BK=16; 256 threads = 8 warps (2m x 4n), warp tile 32x32.
// A fragments loaded via ldmatrix.x4 from a bank-swizzled As[64][32]:
//   element (row r, k): kg=k>>2, kw=k&3, u=(kg+4*(r&1)+((r>>1)&3))&7,
//   word = r*32 + u*4 + kw.  Conflict-free for both STS.128 stores and
//   8-row LDSM phases (verified: store quarter-warps and LDSM rows each
//   cover all 8 bank-units).
// B fragments remain scalar LDS (already conflict-free: banks 8t+q distinct).
// tf32 (RNE) conversion once per element at tile-store; double-buffered via
// registers; one __syncthreads per tile.
// TRANSB=false: B row-major [K,N]; TRANSB=true: B row-major [N,K] (C = A @ B^T).
// Requires M%64==0, N%128==0, K%16==0. Per-z pointers from Batch.
template <bool TRANSB>
__global__ void __launch_bounds__(256, 2)
mma_gemm(Batch bt, int M, int N, int K) {
    const Ptrs pz = bt.p[blockIdx.z];
    const float* __restrict__ A    = pz.A;
    const float* __restrict__ B    = pz.B;
    const float* __restrict__ bias = pz.bias;
    float* __restrict__ C          = pz.C;

    __shared__ __align__(16) float As[2][64][32];
    __shared__ __align__(16) float Bs[2 * 2560];

    const int tid  = threadIdx.x;
    const int lane = tid & 31;
    const int w    = tid >> 5;
    const int wm   = (w >> 2) * 32;  // 0 or 32
    const int wn   = (w & 3) * 32;   // 0,32,64,96
    const int g    = lane >> 2;      // 0..7
    const int tq   = lane & 3;       // 0..3

    const int row0 = blockIdx.y * 64;
    const int col0 = blockIdx.x * 128;

    // per-thread tile staging registers
    float4 ra, rb[2];
    // A: 64x16 = 256 float4 chunks, 1/thread: row tid>>2, k-group tid&3
    const int a_r  = tid >> 2, a_kg = tid & 3;
    // A store swizzle unit
    const int uS = (a_kg + 4 * (a_r & 1) + ((a_r >> 1) & 3)) & 7;
    // B !TRANSB: 16x128 = 512 float4, 2/thread
    const int bn_r0 = tid >> 5,         bn_n0 = (tid & 31) << 2;
    const int bn_r1 = (256 + tid) >> 5, bn_n1 = bn_n0;
    // B TRANSB: 128 n-rows x 16 k = 512 float4, 2/thread
    const int bt_r0 = tid >> 2,         bt_k0 = (tid & 3) << 2;
    const int bt_r1 = (256 + tid) >> 2, bt_k1 = bt_k0;

    // A LDSM lane setup: matrix i = lane>>3, row-in-matrix r7 = lane&7
    const int i4  = lane >> 3, r7 = lane & 7;
    const int rrb = wm + 8 * (i4 & 1) + r7;              // mi=0 row for this lane
    const int Gv  = 4 * (rrb & 1) + ((rrb >> 1) & 3);    // invariant across mi (+16)
    const int kg0 = i4 >> 1;
    const int u0_16 = ((kg0 + Gv) & 7) * 16;             // kk=0 byte offset
    const int u1_16 = ((kg0 + 2 + Gv) & 7) * 16;         // kk=1 byte offset
    const uint32_t As_sh = (uint32_t)__cvta_generic_to_shared(&As[0][0][0]);
    const uint32_t a_lane_base = As_sh + rrb * 128;      // 32 words/row = 128B

    auto load_regs = [&](int t) {
        const int k0 = t << 4;
        ra = *(const float4*)(A + (long)(row0 + a_r) * K + k0 + a_kg * 4);
        if (!TRANSB) {
            rb[0] = *(const float4*)(B + (long)(k0 + bn_r0) * N + col0 + bn_n0);
            rb[1] = *(const float4*)(B + (long)(k0 + bn_r1) * N + col0 + bn_n1);
        } else {
            rb[0] = *(const float4*)(B + (long)(col0 + bt_r0) * K + k0 + bt_k0);
            rb[1] = *(const float4*)(B + (long)(col0 + bt_r1) * K + k0 + bt_k1);
        }
    };

    auto cvt4 = [&](float4 v) {
        uint4 u;
        u.x = f2tf(v.x); u.y = f2tf(v.y); u.z = f2tf(v.z); u.w = f2tf(v.w);
        return u;
    };

    auto store_smem = [&](int buf) {
        *(uint4*)&As[buf][a_r][uS * 4] = cvt4(ra);
        if (!TRANSB) {
            *(uint4*)&Bs[buf * 2560 + bn_r0 * 136 + bn_n0] = cvt4(rb[0]);
            *(uint4*)&Bs[buf * 2560 + bn_r1 * 136 + bn_n1] = cvt4(rb[1]);
        } else {
            *(uint4*)&Bs[buf * 2560 + bt_r0 * 20 + bt_k0] = cvt4(rb[0]);
            *(uint4*)&Bs[buf * 2560 + bt_r1 * 20 + bt_k1] = cvt4(rb[1]);
        }
    };

    float acc[2][4][4];
    #pragma unroll
    for (int mi = 0; mi < 2; mi++)
        #pragma unroll
        for (int ni = 0; ni < 4; ni++)
            #pragma unroll
            for (int e = 0; e < 4; e++) acc[mi][ni][e] = 0.f;

    const int tiles = K >> 4;

    load_regs(0);
    store_smem(0);
    __syncthreads();

    int buf = 0;
    for (int t = 0; t < tiles; t++) {
        if (t + 1 < tiles) load_regs(t + 1);   // LDGs in flight under the MMA loop

        // --- A fragments for the whole tile: 4 x LDSM.x4 ---
        uint32_t af[2][2][4];   // [mi][kk][4]
        {
            const uint32_t abase = a_lane_base + buf * 8192;
            ldsm4(af[0][0], abase + u0_16);
            ldsm4(af[0][1], abase + u1_16);
            ldsm4(af[1][0], abase + 2048 + u0_16);   // mi=1: +16 rows * 128B
            ldsm4(af[1][1], abase + 2048 + u1_16);
        }

        #pragma unroll
        for (int kk = 0; kk < 2; kk++) {
            const int kb = kk * 8;
            uint32_t bfr[4][2];
            #pragma unroll
            for (int ni = 0; ni < 4; ni++) {
                int col = wn + ni * 8 + g;
                if (!TRANSB) {
                    bfr[ni][0] = __float_as_uint(Bs[buf * 2560 + (kb + tq)     * 136 + col]);
                    bfr[ni][1] = __float_as_uint(Bs[buf * 2560 + (kb + tq + 4) * 136 + col]);
                } else {
                    bfr[ni][0] = __float_as_uint(Bs[buf * 2560 + col * 20 + kb + tq]);
                    bfr[ni][1] = __float_as_uint(Bs[buf * 2560 + col * 20 + kb + tq + 4]);
                }
            }
            #pragma unroll
            for (int mi = 0; mi < 2; mi++)
                #pragma unroll
                for (int ni = 0; ni < 4; ni++)
                    MMA_TF32(acc[mi][ni][0], acc[mi][ni][1], acc[mi][ni][2], acc[mi][ni][3],
                             af[mi][kk][0], af[mi][kk][1], af[mi][kk][2], af[mi][kk][3],
                             bfr[ni][0], bfr[ni][1]);
        }

        if (t + 1 < tiles) store_smem(buf ^ 1);  // write other buffer; no WAR on buf
        __syncthreads();
        buf ^= 1;
    }

    // epilogue
    #pragma unroll
    for (int mi = 0; mi < 2; mi++) {
        int r0 = row0 + wm + mi * 16 + g;
        #pragma unroll
        for (int ni = 0; ni < 4; ni++) {
            int cb = col0 + wn + ni * 8 + 2 * tq;
            float b0 = bias ? bias[cb]     : 0.f;
            float b1 = bias ? bias[cb + 1] : 0.f;
            float2 v0 = make_float2(acc[mi][ni][0] + b0, acc[mi][ni][1] + b1);
            float2 v1 = make_float2(acc[mi][ni][2] + b0, acc[mi][ni][3] + b1);
            *(float2*)(C + (long)r0 * N + cb)       = v0;
            *(float2*)(C + (long)(r0 + 8) * N + cb) = v1;
        }
    }
}

// ---------------- adjacency compaction (once per call, reused 24x) ----------------
__global__ void compact_adj_kernel(const float* __restrict__ adj) {
    const int n = blockIdx.x;
    __shared__ int cnt;
    if (threadIdx.x == 0) cnt = 0;
    __syncthreads();
    const float* row = adj + (long)n * NN;
    for (int m = threadIdx.x; m < NN; m += blockDim.x)
        if (row[m] > 0.f) { int p = atomicAdd(&cnt, 1); g_nidx[(long)n * MAXD + p] = m; }
    __syncthreads();
    if (threadIdx.x == 0) g_ncnt[n] = cnt;
}

// ---------------- GAT: s1/s2 scores (one warp per (h,n)) ----------------
__global__ void s12_kernel(const float* __restrict__ a1, const float* __restrict__ a2) {
    int warp = (blockIdx.x * blockDim.x + threadIdx.x) >> 5;
    int lane = threadIdx.x & 31;
    if (warp >= NH_ * NN) return;
    int h = warp / NN;
    const float* w = g_Wh + (long)warp * HD_;
    const float* A1 = a1 + h * HD_;
    const float* A2 = a2 + h * HD_;
    float d1 = 0.f, d2 = 0.f;
    #pragma unroll
    for (int i = lane; i < HD_; i += 32) { float v = w[i]; d1 += v * A1[i]; d2 += v * A2[i]; }
    #pragma unroll
    for (int o = 16; o > 0; o >>= 1) {
        d1 += __shfl_down_sync(0xffffffffu, d1, o);
        d2 += __shfl_down_sync(0xffffffffu, d2, o);
    }
    if (lane == 0) { g_s1[warp] = d1; g_s2[warp] = d2; }
}

// ---------------- GAT attention: sparse softmax + gather (block = (n, h), 128 thr) ----------------
__global__ void gat_attn_kernel() {
    const int n = blockIdx.x, h = blockIdx.y;
    const int tid = threadIdx.x;  // 128
    const int c = g_ncnt[n];
    const int* gidx = g_nidx + (long)n * MAXD;

    __shared__ float sc[MAXD];
    __shared__ int   sidx[MAXD];
    __shared__ float red[128];

    const float s1n = g_s1[h * NN + n];
    const float* s2h = g_s2 + h * NN;

    float mx = -1e30f;
    for (int j = tid; j < c; j += 128) {
        int m = gidx[j];
        sidx[j] = m;
        float e = s1n + s2h[m];
        e = e > 0.f ? e : 0.2f * e;           // leaky_relu(0.2)
        sc[j] = e;
        mx = fmaxf(mx, e);
    }
    red[tid] = mx; __syncthreads();
    for (int o = 64; o > 0; o >>= 1) { if (tid < o) red[tid] = fmaxf(red[tid], red[tid + o]); __syncthreads(); }
    mx = red[0];
    __syncthreads();

    float sm = 0.f;
    for (int j = tid; j < c; j += 128) { float e = expf(sc[j] - mx); sc[j] = e; sm += e; }
    red[tid] = sm; __syncthreads();
    for (int o = 64; o > 0; o >>= 1) { if (tid < o) red[tid] += red[tid + o]; __syncthreads(); }
    const float inv = 1.f / red[0];
    __syncthreads();

    // output feature dim = tid (HD_ == 128)
    float acc = 0.f;
    const float* whh = g_Wh + (long)h * NN * HD_;
    #pragma unroll 4
    for (int j = 0; j < c; j++)
        acc += sc[j] * whh[(long)sidx[j] * HD_ + tid];
    g_hcat[(long)n * GH + h * HD_ + tid] = acc * inv;
}

// ---------------- row-wise LN (+activation) kernels, row width 1024, 256 thr ----------------
// grid = 2*BB rows over g_t1; batch 0 uses (g0,b0), batch 1 uses (g1,b1)
__global__ void ln_gelu2_kernel(float* __restrict__ x,
                                const float* __restrict__ g0, const float* __restrict__ b0,
                                const float* __restrict__ g1, const float* __restrict__ b1) {
    const int row = blockIdx.x, tid = threadIdx.x;
    const float* g = (row < BB) ? g0 : g1;
    const float* b = (row < BB) ? b0 : b1;
    float* xr = x + (long)row * 1024;
    float v[4]; float s = 0.f, ss = 0.f;
    #pragma unroll
    for (int i = 0; i < 4; i++) { v[i] = xr[tid + i * 256]; s += v[i]; ss += v[i] * v[i]; }
    __shared__ float rs[256], rss[256];
    rs[tid] = s; rss[tid] = ss; __syncthreads();
    for (int o = 128; o > 0; o >>= 1) { if (tid < o) { rs[tid] += rs[tid + o]; rss[tid] += rss[tid + o]; } __syncthreads(); }
    float mean = rs[0] * (1.f / 1024.f);
    float var  = rss[0] * (1.f / 1024.f) - mean * mean;
    float rstd = rsqrtf(var + 1e-5f);
    #pragma unroll
    for (int i = 0; i < 4; i++) {
        int cidx = tid + i * 256;
        float t = (v[i] - mean) * rstd * g[cidx] + b[cidx];
        xr[cidx] = 0.5f * t * (1.f + erff(t * 0.70710678118654752f));  // exact gelu
    }
}

__global__ void ln_elu_res_kernel(const float* __restrict__ hin, const float* __restrict__ g,
                                  const float* __restrict__ b, float* __restrict__ x) {
    const int row = blockIdx.x, tid = threadIdx.x;
    const float* hr = hin + (long)row * 1024;
    float* xr = x + (long)row * 1024;
    float v[4]; float s = 0.f, ss = 0.f;
    #pragma unroll
    for (int i = 0; i < 4; i++) { v[i] = hr[tid + i * 256]; s += v[i]; ss += v[i] * v[i]; }
    __shared__ float rs[256], rss[256];
    rs[tid] = s; rss[tid] = ss; __syncthreads();
    for (int o = 128; o > 0; o >>= 1) { if (tid < o) { rs[tid] += rs[tid + o]; rss[tid] += rss[tid + o]; } __syncthreads(); }
    float mean = rs[0] * (1.f / 1024.f);
    float var  = rss[0] * (1.f / 1024.f) - mean * mean;
    float rstd = rsqrtf(var + 1e-5f);
    #pragma unroll
    for (int i = 0; i < 4; i++) {
        int cidx = tid + i * 256;
        float t = (v[i] - mean) * rstd * g[cidx] + b[cidx];
        t = t > 0.f ? t : expm1f(t);          // elu
        xr[cidx] += t;                        // residual
    }
}

__global__ void l2norm_kernel(float* __restrict__ x) {
    const int row = blockIdx.x, tid = threadIdx.x;
    float* xr = x + (long)row * 1024;
    float v[4]; float ss = 0.f;
    #pragma unroll
    for (int i = 0; i < 4; i++) { v[i] = xr[tid + i * 256]; ss += v[i] * v[i]; }
    __shared__ float rss[256];
    rss[tid] = ss; __syncthreads();
    for (int o = 128; o > 0; o >>= 1) { if (tid < o) rss[tid] += rss[tid + o]; __syncthreads(); }
    float nrm = sqrtf(rss[0]);
    float inv = 1.f / fmaxf(nrm, 1e-12f);
    #pragma unroll
    for (int i = 0; i < 4; i++) xr[tid + i * 256] = v[i] * inv;
}

// ---------------- InfoNCE: per-row logsumexp over [pos, row] ----------------
__global__ void infonce_kernel() {
    const int i = blockIdx.x, tid = threadIdx.x;  // 256 thr, BB rows
    const float* row = g_S + (long)i * BB;
    const float pos = row[i] * INV_TEMP;

    __shared__ float red[256];
    float mx = -1e30f;
    for (int j = tid; j < BB; j += 256) mx = fmaxf(mx, row[j] * INV_TEMP);
    red[tid] = mx; __syncthreads();
    for (int o = 128; o > 0; o >>= 1) { if (tid < o) red[tid] = fmaxf(red[tid], red[tid + o]); __syncthreads(); }
    mx = red[0];
    __syncthreads();

    float sm = 0.f;
    for (int j = tid; j < BB; j += 256) sm += expf(row[j] * INV_TEMP - mx);
    red[tid] = sm; __syncthreads();
    for (int o = 128; o > 0; o >>= 1) { if (tid < o) red[tid] += red[tid + o]; __syncthreads(); }

    if (tid == 0) {
        float total = red[0] + expf(pos - mx);   // duplicate pos logit (concat)
        float loss = logf(total) + mx - pos;
        atomicAdd(&g_acc[0], (double)loss);
    }
}

// ---------------- Laplacian regularizer: sum(G * LG) ----------------
__global__ void lapdot_kernel() {
    const int n = NN * ED;
    double local = 0.0;
    for (int i = blockIdx.x * blockDim.x + threadIdx.x; i < n; i += gridDim.x * blockDim.x)
        local += (double)g_G[i] * (double)g_LG[i];
    __shared__ double rd[256];
    rd[threadIdx.x] = local; __syncthreads();
    for (int o = 128; o > 0; o >>= 1) { if (threadIdx.x < o) rd[threadIdx.x] += rd[threadIdx.x + o]; __syncthreads(); }
    if (threadIdx.x == 0) atomicAdd(&g_acc[1], rd[0]);
}

__global__ void finalize_kernel(float* out, int out_size) {
    double info = g_acc[0] / (double)BB;
    double lap  = g_acc[1] / (double)NN;
    double vals[3] = { info + LAPW * lap, info, lap };
    for (int i = 0; i < out_size && i < 3; i++) out[i] = (float)vals[i];
}

// ---------------- launch ----------------
extern "C" void kernel_launch(void* const* d_in, const int* in_sizes, int n_in,
                              void* d_out, int out_size) {
    const float* query = (const float*)d_in[0];
    const float* doc   = (const float*)d_in[1];
    const float* node  = (const float*)d_in[2];
    const float* adj   = (const float*)d_in[3];
    const float* lapl  = (const float*)d_in[4];
    const float* qW1 = (const float*)d_in[5];  const float* qb1 = (const float*)d_in[6];
    const float* qg  = (const float*)d_in[7];  const float* qbt = (const float*)d_in[8];
    const float* qW2 = (const float*)d_in[9];  const float* qb2 = (const float*)d_in[10];
    const float* dW1 = (const float*)d_in[11]; const float* db1 = (const float*)d_in[12];
    const float* dg  = (const float*)d_in[13]; const float* dbt = (const float*)d_in[14];
    const float* dW2 = (const float*)d_in[15]; const float* db2 = (const float*)d_in[16];
    const float* gatW = (const float*)d_in[17];
    const float* a1   = (const float*)d_in[18];
    const float* a2   = (const float*)d_in[19];
    const float* ln_g = (const float*)d_in[20];
    const float* ln_b = (const float*)d_in[21];
    const float* poW  = (const float*)d_in[22];
    const float* pob  = (const float*)d_in[23];
    float* out = (float*)d_out;

    float *px, *pWh, *phcat, *pG, *pLG, *pt1, *pqp, *pS;
    cudaGetSymbolAddress((void**)&px,    g_x);
    cudaGetSymbolAddress((void**)&pWh,   g_Wh);
    cudaGetSymbolAddress((void**)&phcat, g_hcat);
    cudaGetSymbolAddress((void**)&pG,    g_G);
    cudaGetSymbolAddress((void**)&pLG,   g_LG);
    cudaGetSymbolAddress((void**)&pt1,   g_t1);
    cudaGetSymbolAddress((void**)&pqp,   g_qp);
    cudaGetSymbolAddress((void**)&pS,    g_S);

    const long QO = (long)BB * ED;   // batch offset

    zero_acc_kernel<<<1, 1>>>();
    compact_adj_kernel<<<NN, 256>>>(adj);
    copy_kernel<<<2048, 512>>>(node, px, NN * GH);

    // ---- GNN layers ----
    for (int l = 0; l < NL_; l++) {
        Batch bw = {};
        for (int h = 0; h < NH_; h++) {
            bw.p[h].A = px;
            bw.p[h].B = gatW + (long)l * NH_ * ED * HD_ + (long)h * ED * HD_;
            bw.p[h].bias = nullptr;
            bw.p[h].C = pWh + (long)h * NN * HD_;
        }
        mma_gemm<false><<<dim3(HD_ / 128, NN / 64, NH_), 256>>>(bw, NN, HD_, GH);
        s12_kernel<<<(NH_ * NN * 32 + 255) / 256, 256>>>(a1 + l * NH_ * HD_, a2 + l * NH_ * HD_);
        gat_attn_kernel<<<dim3(NN, NH_), 128>>>();
        ln_elu_res_kernel<<<NN, 256>>>(phcat, ln_g + l * GH, ln_b + l * GH, px);
    }

    // graph_embeds = x @ poW + pob ; LG = laplacian @ G
    { Batch b = {}; b.p[0] = { px, poW, pob, pG };
      mma_gemm<false><<<dim3(ED / 128, NN / 64, 1), 256>>>(b, NN, ED, GH); }
    { Batch b = {}; b.p[0] = { lapl, pG, nullptr, pLG };
      mma_gemm<false><<<dim3(ED / 128, NN / 64, 1), 256>>>(b, NN, ED, NN); }
    lapdot_kernel<<<2048, 256>>>();

    // ---- q + doc MLPs, batched z=2 ----
    { Batch b = {};
      b.p[0] = { query, qW1, qb1, pt1 };
      b.p[1] = { doc,   dW1, db1, pt1 + QO };
      mma_gemm<false><<<dim3(ED / 128, BB / 64, 2), 256>>>(b, BB, ED, ED); }
    ln_gelu2_kernel<<<2 * BB, 256>>>(pt1, qg, qbt, dg, dbt);
    { Batch b = {};
      b.p[0] = { pt1,      qW2, qb2, pqp };
      b.p[1] = { pt1 + QO, dW2, db2, pqp + QO };
      mma_gemm<false><<<dim3(ED / 128, BB / 64, 2), 256>>>(b, BB, ED, ED); }
    l2norm_kernel<<<2 * BB, 256>>>(pqp);

    // ---- similarities + losses ----
    { Batch b = {}; b.p[0] = { pqp, pqp + QO, nullptr, pS };
      mma_gemm<true><<<dim3(BB / 128, BB / 64, 1), 256>>>(b, BB, BB, ED); }
    infonce_kernel<<<BB, 256>>>();

    finalize_kernel<<<1, 1>>>(out, out_size);
}